// round 1
// baseline (speedup 1.0000x reference)
#include <cuda_runtime.h>
#include <math.h>

#define BSZ 2
#define TSEQ 4096
#define CDIM 768
#define NH 12
#define HD 64
#define MTOK (BSZ * TSEQ)      // 8192
#define NQKV (3 * CDIM)        // 2304
#define BH (BSZ * NH)          // 24

// Scratch (allocation-free rule: device globals)
__device__ float g_Q[(size_t)BH * TSEQ * HD];   // [b*H+h, T, D]
__device__ float g_K[(size_t)BH * TSEQ * HD];
__device__ float g_V[(size_t)BH * TSEQ * HD];
__device__ float g_Y[(size_t)MTOK * CDIM];      // attention out, [B*T, C]

// ---------------------------------------------------------------------------
// Kernel 1: QKV GEMM  A[8192,768] @ W[768,2304] + bias -> scatter Q/K/V
// 128x128 tile, BK=8, 256 threads, 8x8 per thread.
// ---------------------------------------------------------------------------
__global__ __launch_bounds__(256) void qkv_gemm_kernel(const float* __restrict__ A,
                                                       const float* __restrict__ W,
                                                       const float* __restrict__ bias)
{
    __shared__ float As[8][128];
    __shared__ float Bs[8][128];

    const int n0 = blockIdx.x * 128;
    const int m0 = blockIdx.y * 128;
    const int tid = (int)threadIdx.x;
    const int tx = tid & 15;       // 0..15 -> n
    const int ty = tid >> 4;       // 0..15 -> m

    float acc[8][8];
#pragma unroll
    for (int i = 0; i < 8; i++)
#pragma unroll
        for (int j = 0; j < 8; j++) acc[i][j] = 0.f;

    const int ar = tid >> 1;            // 0..127 (row within A tile)
    const int ac = (tid & 1) * 4;       // 0 or 4 (k within A tile)
    const int br = tid >> 5;            // 0..7  (k within B tile)
    const int bc = (tid & 31) * 4;      // 0..124 (n within B tile)

    for (int k0 = 0; k0 < CDIM; k0 += 8) {
        float4 av = *(const float4*)(A + (size_t)(m0 + ar) * CDIM + k0 + ac);
        float4 bv = *(const float4*)(W + (size_t)(k0 + br) * NQKV + n0 + bc);
        As[ac + 0][ar] = av.x;
        As[ac + 1][ar] = av.y;
        As[ac + 2][ar] = av.z;
        As[ac + 3][ar] = av.w;
        *(float4*)(&Bs[br][bc]) = bv;
        __syncthreads();
#pragma unroll
        for (int k = 0; k < 8; k++) {
            float a[8], b[8];
#pragma unroll
            for (int i = 0; i < 8; i++) a[i] = As[k][ty * 8 + i];
#pragma unroll
            for (int j = 0; j < 8; j++) b[j] = Bs[k][tx * 8 + j];
#pragma unroll
            for (int i = 0; i < 8; i++)
#pragma unroll
                for (int j = 0; j < 8; j++) acc[i][j] = fmaf(a[i], b[j], acc[i][j]);
        }
        __syncthreads();
    }

    // Epilogue: add bias, scatter into Q/K/V head-major [b*H+h, T, D]
#pragma unroll
    for (int i = 0; i < 8; i++) {
        const int m = m0 + ty * 8 + i;
        const int b = m >> 12;          // /4096
        const int t = m & 4095;
#pragma unroll
        for (int j = 0; j < 8; j++) {
            const int n = n0 + tx * 8 + j;
            const float v = acc[i][j] + bias[n];
            const int sel = n / CDIM;            // 0=Q,1=K,2=V
            const int r = n - sel * CDIM;
            const int h = r >> 6;
            const int d = r & 63;
            float* dst = (sel == 0) ? g_Q : ((sel == 1) ? g_K : g_V);
            dst[((size_t)(b * NH + h) * TSEQ + t) * HD + d] = v;
        }
    }
}

// ---------------------------------------------------------------------------
// Kernel 2: causal flash attention, fp32, online softmax.
// One block per (q-tile of 64 rows, b*h). 256 threads, 4x4 per thread for
// both S = Q K^T and O += P V. Shared buffers use stride 65 (bank padding).
// ---------------------------------------------------------------------------
#define SSTR 65

__global__ __launch_bounds__(256) void attn_kernel()
{
    extern __shared__ float sm[];
    float* Qs   = sm;                 // [64][65]
    float* KVs  = Qs  + 64 * SSTR;    // [64][65]  (holds K, then V)
    float* Ps   = KVs + 64 * SSTR;    // [64][65]  (S, then P)
    float* rowm = Ps  + 64 * SSTR;    // [64]
    float* rowl = rowm + 64;          // [64]
    float* rowc = rowl + 64;          // [64]

    const int qt  = (int)blockIdx.x;  // 0..63
    const int bh  = (int)blockIdx.y;  // 0..23
    const int tid = (int)threadIdx.x;
    const int tx  = tid & 15;
    const int ty  = tid >> 4;

    const float* Qg = g_Q + (size_t)bh * TSEQ * HD + (size_t)qt * 64 * HD;
    const float* Kg = g_K + (size_t)bh * TSEQ * HD;
    const float* Vg = g_V + (size_t)bh * TSEQ * HD;

    // Load Q tile (scaled by 1/sqrt(D) = 0.125)
#pragma unroll
    for (int it = 0; it < 4; it++) {
        const int off = tid * 4 + it * 1024;   // 0..4095
        const int r = off >> 6, c = off & 63;
        float4 v = *(const float4*)(Qg + off);
        Qs[r * SSTR + c + 0] = v.x * 0.125f;
        Qs[r * SSTR + c + 1] = v.y * 0.125f;
        Qs[r * SSTR + c + 2] = v.z * 0.125f;
        Qs[r * SSTR + c + 3] = v.w * 0.125f;
    }
    if (tid < 64) { rowm[tid] = -1e30f; rowl[tid] = 0.f; }

    float o[4][4];
#pragma unroll
    for (int i = 0; i < 4; i++)
#pragma unroll
        for (int j = 0; j < 4; j++) o[i][j] = 0.f;

    __syncthreads();

    for (int jt = 0; jt <= qt; jt++) {
        // ---- load K tile into KVs
        const float* Kt = Kg + (size_t)jt * 64 * HD;
#pragma unroll
        for (int it = 0; it < 4; it++) {
            const int off = tid * 4 + it * 1024;
            const int r = off >> 6, c = off & 63;
            float4 v = *(const float4*)(Kt + off);
            KVs[r * SSTR + c + 0] = v.x;
            KVs[r * SSTR + c + 1] = v.y;
            KVs[r * SSTR + c + 2] = v.z;
            KVs[r * SSTR + c + 3] = v.w;
        }
        __syncthreads();

        // ---- S = Q K^T (4x4 per thread)
        float s[4][4];
#pragma unroll
        for (int i = 0; i < 4; i++)
#pragma unroll
            for (int j = 0; j < 4; j++) s[i][j] = 0.f;

#pragma unroll 4
        for (int d = 0; d < 64; d++) {
            float a[4], b[4];
#pragma unroll
            for (int i = 0; i < 4; i++) a[i] = Qs[(ty * 4 + i) * SSTR + d];
#pragma unroll
            for (int j = 0; j < 4; j++) b[j] = KVs[(tx * 4 + j) * SSTR + d];
#pragma unroll
            for (int i = 0; i < 4; i++)
#pragma unroll
                for (int j = 0; j < 4; j++) s[i][j] = fmaf(a[i], b[j], s[i][j]);
        }
        __syncthreads();   // done reading K

        // ---- store S; load V into KVs (overwrites K)
#pragma unroll
        for (int i = 0; i < 4; i++)
#pragma unroll
            for (int j = 0; j < 4; j++)
                Ps[(ty * 4 + i) * SSTR + tx * 4 + j] = s[i][j];

        const float* Vt = Vg + (size_t)jt * 64 * HD;
#pragma unroll
        for (int it = 0; it < 4; it++) {
            const int off = tid * 4 + it * 1024;
            const int r = off >> 6, c = off & 63;
            float4 v = *(const float4*)(Vt + off);
            KVs[r * SSTR + c + 0] = v.x;
            KVs[r * SSTR + c + 1] = v.y;
            KVs[r * SSTR + c + 2] = v.z;
            KVs[r * SSTR + c + 3] = v.w;
        }
        __syncthreads();

        // ---- online softmax row pass (one thread per q-row)
        if (tid < 64) {
            const int jmax = (jt == qt) ? (tid + 1) : 64;   // causal mask
            float* prow = &Ps[tid * SSTR];
            float mo = rowm[tid];
            float mx = mo;
            for (int j = 0; j < jmax; j++) mx = fmaxf(mx, prow[j]);
            const float corr = __expf(mo - mx);
            float lsum = 0.f;
            for (int j = 0; j < jmax; j++) {
                const float p = __expf(prow[j] - mx);
                prow[j] = p;
                lsum += p;
            }
            for (int j = jmax; j < 64; j++) prow[j] = 0.f;
            rowm[tid] = mx;
            rowl[tid] = rowl[tid] * corr + lsum;
            rowc[tid] = corr;
        }
        __syncthreads();

        // ---- O = O*corr + P @ V  (4 rows x 4 dcols per thread)
        float cr[4];
#pragma unroll
        for (int i = 0; i < 4; i++) cr[i] = rowc[ty * 4 + i];
#pragma unroll
        for (int i = 0; i < 4; i++)
#pragma unroll
            for (int j = 0; j < 4; j++) o[i][j] *= cr[i];

#pragma unroll 4
        for (int j = 0; j < 64; j++) {
            float p[4], vv[4];
#pragma unroll
            for (int i = 0; i < 4; i++) p[i] = Ps[(ty * 4 + i) * SSTR + j];
#pragma unroll
            for (int jj = 0; jj < 4; jj++) vv[jj] = KVs[j * SSTR + tx * 4 + jj];
#pragma unroll
            for (int i = 0; i < 4; i++)
#pragma unroll
                for (int jj = 0; jj < 4; jj++) o[i][jj] = fmaf(p[i], vv[jj], o[i][jj]);
        }
        __syncthreads();   // protect KVs/Ps for next tile
    }

    // ---- epilogue: normalize and write to g_Y in [B*T, C] layout
    const int b = bh / NH;
    const int h = bh % NH;
#pragma unroll
    for (int i = 0; i < 4; i++) {
        const int trow = qt * 64 + ty * 4 + i;
        const float invl = 1.f / rowl[ty * 4 + i];
        float* dst = g_Y + (size_t)(b * TSEQ + trow) * CDIM + h * 64 + tx * 4;
#pragma unroll
        for (int jj = 0; jj < 4; jj++) dst[jj] = o[i][jj] * invl;
    }
}

// ---------------------------------------------------------------------------
// Kernel 3: output projection  g_Y[8192,768] @ Wproj[768,768] + bias -> out
// ---------------------------------------------------------------------------
__global__ __launch_bounds__(256) void proj_gemm_kernel(const float* __restrict__ W,
                                                        const float* __restrict__ bias,
                                                        float* __restrict__ out)
{
    __shared__ float As[8][128];
    __shared__ float Bs[8][128];

    const int n0 = blockIdx.x * 128;
    const int m0 = blockIdx.y * 128;
    const int tid = (int)threadIdx.x;
    const int tx = tid & 15;
    const int ty = tid >> 4;

    float acc[8][8];
#pragma unroll
    for (int i = 0; i < 8; i++)
#pragma unroll
        for (int j = 0; j < 8; j++) acc[i][j] = 0.f;

    const int ar = tid >> 1;
    const int ac = (tid & 1) * 4;
    const int br = tid >> 5;
    const int bc = (tid & 31) * 4;

    const float* A = g_Y;

    for (int k0 = 0; k0 < CDIM; k0 += 8) {
        float4 av = *(const float4*)(A + (size_t)(m0 + ar) * CDIM + k0 + ac);
        float4 bv = *(const float4*)(W + (size_t)(k0 + br) * CDIM + n0 + bc);
        As[ac + 0][ar] = av.x;
        As[ac + 1][ar] = av.y;
        As[ac + 2][ar] = av.z;
        As[ac + 3][ar] = av.w;
        *(float4*)(&Bs[br][bc]) = bv;
        __syncthreads();
#pragma unroll
        for (int k = 0; k < 8; k++) {
            float a[8], b[8];
#pragma unroll
            for (int i = 0; i < 8; i++) a[i] = As[k][ty * 8 + i];
#pragma unroll
            for (int j = 0; j < 8; j++) b[j] = Bs[k][tx * 8 + j];
#pragma unroll
            for (int i = 0; i < 8; i++)
#pragma unroll
                for (int j = 0; j < 8; j++) acc[i][j] = fmaf(a[i], b[j], acc[i][j]);
        }
        __syncthreads();
    }

#pragma unroll
    for (int i = 0; i < 8; i++) {
        const int m = m0 + ty * 8 + i;
#pragma unroll
        for (int j = 0; j < 8; j++) {
            const int n = n0 + tx * 8 + j;
            out[(size_t)m * CDIM + n] = acc[i][j] + bias[n];
        }
    }
}

// ---------------------------------------------------------------------------
extern "C" void kernel_launch(void* const* d_in, const int* in_sizes, int n_in,
                              void* d_out, int out_size)
{
    const float* x     = (const float*)d_in[0];
    const float* Wqkv  = (const float*)d_in[1];
    const float* bqkv  = (const float*)d_in[2];
    const float* Wproj = (const float*)d_in[3];
    const float* bproj = (const float*)d_in[4];
    float* out = (float*)d_out;

    // attention dynamic smem: 3 tiles of 64x65 + 3x64 row stats
    const size_t attn_smem = (3 * 64 * SSTR + 3 * 64) * sizeof(float);  // ~50.7 KB
    cudaFuncSetAttribute(attn_kernel, cudaFuncAttributeMaxDynamicSharedMemorySize,
                         (int)attn_smem);

    qkv_gemm_kernel<<<dim3(NQKV / 128, MTOK / 128), 256>>>(x, Wqkv, bqkv);
    attn_kernel<<<dim3(TSEQ / 64, BH), 256, attn_smem>>>();
    proj_gemm_kernel<<<dim3(CDIM / 128, MTOK / 128), 256>>>(Wproj, bproj, out);
}

// round 2
// speedup vs baseline: 2.1338x; 2.1338x over previous
#include <cuda_runtime.h>
#include <math.h>

#define BSZ 2
#define TSEQ 4096
#define CDIM 768
#define NH 12
#define HD 64
#define MTOK (BSZ * TSEQ)      // 8192
#define NQKV (3 * CDIM)        // 2304
#define BH (BSZ * NH)          // 24

// Scratch (allocation-free rule: device globals)
__device__ float g_Q[(size_t)BH * TSEQ * HD];   // [b*H+h, T, D]
__device__ float g_K[(size_t)BH * TSEQ * HD];
__device__ float g_V[(size_t)BH * TSEQ * HD];
__device__ float g_Y[(size_t)MTOK * CDIM];      // attention out, [B*T, C]

// ---------------------------------------------------------------------------
// TF32 helpers
// ---------------------------------------------------------------------------
__device__ __forceinline__ unsigned f2tf(float f) {
    unsigned r;
    asm("cvt.rna.tf32.f32 %0, %1;" : "=r"(r) : "f"(f));
    return r;
}

// D += A(16x8) * B(8x8), tf32 in / fp32 acc. a[4], b[2], c[4] per thread.
__device__ __forceinline__ void mma8(float* c, const unsigned* a, const unsigned* b) {
    asm volatile(
        "mma.sync.aligned.m16n8k8.row.col.f32.tf32.tf32.f32 "
        "{%0,%1,%2,%3}, {%4,%5,%6,%7}, {%8,%9}, {%0,%1,%2,%3};"
        : "+f"(c[0]), "+f"(c[1]), "+f"(c[2]), "+f"(c[3])
        : "r"(a[0]), "r"(a[1]), "r"(a[2]), "r"(a[3]), "r"(b[0]), "r"(b[1]));
}

// ---------------------------------------------------------------------------
// Kernel 1: QKV GEMM (tensor core tf32)
// A[8192,768] @ W[768,2304] + bias -> scatter into head-major Q/K/V.
// 128x128x32 tile, 256 threads (8 warps, warp tile 64x32).
// ---------------------------------------------------------------------------
#define GSTR 136   // smem row stride (floats); 136 % 32 == 8 -> conflict-free frags

__device__ __forceinline__ void scatter_qkv2(int m, int n, float v0, float v1) {
    const int b = m >> 12;
    const int tt = m & 4095;
    const int sel = n / CDIM;            // 0=Q,1=K,2=V
    const int r = n - sel * CDIM;
    const int h = r >> 6;
    const int d = r & 63;
    float* dst = (sel == 0) ? g_Q : ((sel == 1) ? g_K : g_V);
    *(float2*)&dst[((size_t)(b * NH + h) * TSEQ + tt) * HD + d] = make_float2(v0, v1);
}

__global__ __launch_bounds__(256) void qkv_gemm_tc(const float* __restrict__ A,
                                                   const float* __restrict__ W,
                                                   const float* __restrict__ bias)
{
    __shared__ unsigned As[32 * GSTR];   // [k][m]
    __shared__ unsigned Bs[32 * GSTR];   // [k][n]

    const int tid = (int)threadIdx.x;
    const int lane = tid & 31;
    const int wid = tid >> 5;
    const int g = lane >> 2;
    const int t = lane & 3;
    const int m0 = blockIdx.y * 128;
    const int n0 = blockIdx.x * 128;
    const int m0w = (wid & 1) * 64;
    const int n0w = (wid >> 1) * 32;

    float acc[4][4][4];
#pragma unroll
    for (int i = 0; i < 4; i++)
#pragma unroll
        for (int j = 0; j < 4; j++)
#pragma unroll
            for (int k = 0; k < 4; k++) acc[i][j][k] = 0.f;

    for (int kb = 0; kb < CDIM; kb += 32) {
        // A tile 128x32, transposed store into As[k][m]
#pragma unroll
        for (int fi = 0; fi < 4; fi++) {
            const int u = fi * 256 + tid;
            const int row = u >> 3;
            const int kc = (u & 7) * 4;
            float4 v = *(const float4*)(A + (size_t)(m0 + row) * CDIM + kb + kc);
            As[(kc + 0) * GSTR + row] = f2tf(v.x);
            As[(kc + 1) * GSTR + row] = f2tf(v.y);
            As[(kc + 2) * GSTR + row] = f2tf(v.z);
            As[(kc + 3) * GSTR + row] = f2tf(v.w);
        }
        // B tile 32x128, direct store Bs[k][n]
#pragma unroll
        for (int fi = 0; fi < 4; fi++) {
            const int u = fi * 256 + tid;
            const int row = u >> 5;
            const int nc = (u & 31) * 4;
            float4 v = *(const float4*)(W + (size_t)(kb + row) * NQKV + n0 + nc);
            unsigned* dst = &Bs[row * GSTR + nc];
            dst[0] = f2tf(v.x); dst[1] = f2tf(v.y);
            dst[2] = f2tf(v.z); dst[3] = f2tf(v.w);
        }
        __syncthreads();

#pragma unroll
        for (int ks = 0; ks < 4; ks++) {
            const int kk = ks * 8 + t;
            unsigned a[4][4], b[4][2];
#pragma unroll
            for (int mf = 0; mf < 4; mf++) {
                const int base = kk * GSTR + m0w + mf * 16 + g;
                a[mf][0] = As[base];
                a[mf][1] = As[base + 8];
                a[mf][2] = As[base + 4 * GSTR];
                a[mf][3] = As[base + 4 * GSTR + 8];
            }
#pragma unroll
            for (int nf = 0; nf < 4; nf++) {
                const int base = kk * GSTR + n0w + nf * 8 + g;
                b[nf][0] = Bs[base];
                b[nf][1] = Bs[base + 4 * GSTR];
            }
#pragma unroll
            for (int mf = 0; mf < 4; mf++)
#pragma unroll
                for (int nf = 0; nf < 4; nf++) mma8(acc[mf][nf], a[mf], b[nf]);
        }
        __syncthreads();
    }

    // Epilogue: bias + scatter (float2 pairs stay within one head segment)
#pragma unroll
    for (int mf = 0; mf < 4; mf++) {
        const int r0 = m0 + m0w + mf * 16 + g;
#pragma unroll
        for (int nf = 0; nf < 4; nf++) {
            const int c0 = n0 + n0w + nf * 8 + 2 * t;
            const float b0 = bias[c0], b1 = bias[c0 + 1];
            scatter_qkv2(r0,     c0, acc[mf][nf][0] + b0, acc[mf][nf][1] + b1);
            scatter_qkv2(r0 + 8, c0, acc[mf][nf][2] + b0, acc[mf][nf][3] + b1);
        }
    }
}

// ---------------------------------------------------------------------------
// Kernel 2: causal flash attention, tf32 tensor cores.
// Block = (q-tile 64, b*h). 8 warps in 4x2 grid: warp = 16 q-rows x 32 cols.
// Softmax: 4 threads per row with shuffle reductions.
// ---------------------------------------------------------------------------
#define QSTR 68   // 68 % 32 == 4  -> conflict-free row-major A-frag loads
#define KSTR 72   // 72 % 32 == 8  -> conflict-free k-major B-frag loads

__global__ __launch_bounds__(256) void attn_tc()
{
    extern __shared__ float smf[];
    unsigned* Qs = (unsigned*)smf;            // [64][QSTR] tf32, Q*0.125
    unsigned* Ks = Qs + 64 * QSTR;            // [d][kv] = [64][KSTR] tf32
    unsigned* Vs = Ks + 64 * KSTR;            // [kv][d] = [64][KSTR] tf32
    float*    Ss = (float*)(Vs + 64 * KSTR);  // [64][QSTR]: S (fp32), then P (tf32 bits)
    unsigned* Ps = (unsigned*)Ss;
    float* rowm = Ss + 64 * QSTR;
    float* rowl = rowm + 64;
    float* rowc = rowl + 64;

    const int qt = (int)blockIdx.x;
    const int bh = (int)blockIdx.y;
    const int tid = (int)threadIdx.x;
    const int lane = tid & 31;
    const int wid = tid >> 5;
    const int g = lane >> 2;
    const int t = lane & 3;
    const int wr = wid >> 1;       // 0..3 -> q rows wr*16
    const int wc = wid & 1;        // 0..1 -> cols wc*32

    const float* Qg = g_Q + (size_t)bh * TSEQ * HD + (size_t)qt * 64 * HD;
    const float* Kg = g_K + (size_t)bh * TSEQ * HD;
    const float* Vg = g_V + (size_t)bh * TSEQ * HD;

    // Load + scale Q
#pragma unroll
    for (int fi = 0; fi < 4; fi++) {
        const int u = fi * 256 + tid;
        const int r = u >> 4;
        const int c = (u & 15) * 4;
        float4 v = *(const float4*)(Qg + r * 64 + c);
        unsigned* dst = &Qs[r * QSTR + c];
        dst[0] = f2tf(v.x * 0.125f); dst[1] = f2tf(v.y * 0.125f);
        dst[2] = f2tf(v.z * 0.125f); dst[3] = f2tf(v.w * 0.125f);
    }
    if (tid < 64) { rowm[tid] = -1e30f; rowl[tid] = 0.f; }

    float o[4][4];
#pragma unroll
    for (int i = 0; i < 4; i++)
#pragma unroll
        for (int j = 0; j < 4; j++) o[i][j] = 0.f;

    __syncthreads();

    for (int jt = 0; jt <= qt; jt++) {
        // ---- load K (transposed) and V tiles
#pragma unroll
        for (int fi = 0; fi < 4; fi++) {
            const int u = fi * 256 + tid;
            const int r = u >> 4;
            const int c = (u & 15) * 4;
            float4 kv = *(const float4*)(Kg + (size_t)(jt * 64 + r) * 64 + c);
            Ks[(c + 0) * KSTR + r] = f2tf(kv.x);
            Ks[(c + 1) * KSTR + r] = f2tf(kv.y);
            Ks[(c + 2) * KSTR + r] = f2tf(kv.z);
            Ks[(c + 3) * KSTR + r] = f2tf(kv.w);
            float4 vv = *(const float4*)(Vg + (size_t)(jt * 64 + r) * 64 + c);
            unsigned* vd = &Vs[r * KSTR + c];
            vd[0] = f2tf(vv.x); vd[1] = f2tf(vv.y);
            vd[2] = f2tf(vv.z); vd[3] = f2tf(vv.w);
        }
        __syncthreads();

        // ---- S = Q K^T (tensor)
        float s[4][4];
#pragma unroll
        for (int i = 0; i < 4; i++)
#pragma unroll
            for (int j = 0; j < 4; j++) s[i][j] = 0.f;

#pragma unroll
        for (int ks = 0; ks < 8; ks++) {
            const int kk = ks * 8 + t;
            unsigned a[4];
            const int abase = (wr * 16 + g) * QSTR + kk;
            a[0] = Qs[abase];
            a[1] = Qs[abase + 8 * QSTR];
            a[2] = Qs[abase + 4];
            a[3] = Qs[abase + 8 * QSTR + 4];
#pragma unroll
            for (int nf = 0; nf < 4; nf++) {
                unsigned b[2];
                const int bbase = kk * KSTR + wc * 32 + nf * 8 + g;
                b[0] = Ks[bbase];
                b[1] = Ks[bbase + 4 * KSTR];
                mma8(s[nf], a, b);
            }
        }

        // ---- store S (fp32)
#pragma unroll
        for (int nf = 0; nf < 4; nf++) {
            const int r0 = wr * 16 + g;
            const int c0 = wc * 32 + nf * 8 + 2 * t;
            *(float2*)&Ss[r0 * QSTR + c0]       = make_float2(s[nf][0], s[nf][1]);
            *(float2*)&Ss[(r0 + 8) * QSTR + c0] = make_float2(s[nf][2], s[nf][3]);
        }
        __syncthreads();

        // ---- online softmax: 4 threads per row, 16 cols each
        {
            const int r = tid >> 2;
            const int seg = tid & 3;
            const int grow = qt * 64 + r;
            const int jc0 = jt * 64 + seg * 16;
            float vals[16];
            float* row = &Ss[r * QSTR + seg * 16];
#pragma unroll
            for (int i = 0; i < 16; i += 4) {
                float4 v4 = *(float4*)&row[i];
                vals[i] = v4.x; vals[i + 1] = v4.y; vals[i + 2] = v4.z; vals[i + 3] = v4.w;
            }
#pragma unroll
            for (int i = 0; i < 16; i++)
                if (jc0 + i > grow) vals[i] = -1e30f;   // causal mask (no-op for jt<qt)

            float mx = -1e30f;
#pragma unroll
            for (int i = 0; i < 16; i++) mx = fmaxf(mx, vals[i]);
            mx = fmaxf(mx, __shfl_xor_sync(0xffffffffu, mx, 1));
            mx = fmaxf(mx, __shfl_xor_sync(0xffffffffu, mx, 2));

            const float mo = rowm[r];
            const float nm = fmaxf(mo, mx);
            const float corr = __expf(mo - nm);
            float ls = 0.f;
#pragma unroll
            for (int i = 0; i < 16; i++) {
                const float p = __expf(vals[i] - nm);
                vals[i] = p;
                ls += p;
            }
            ls += __shfl_xor_sync(0xffffffffu, ls, 1);
            ls += __shfl_xor_sync(0xffffffffu, ls, 2);
            if (seg == 0) {
                rowm[r] = nm;
                rowl[r] = rowl[r] * corr + ls;
                rowc[r] = corr;
            }
            // store P as tf32 bits
            unsigned* prow = &Ps[r * QSTR + seg * 16];
#pragma unroll
            for (int i = 0; i < 16; i += 4) {
                uint4 u4;
                u4.x = f2tf(vals[i]);     u4.y = f2tf(vals[i + 1]);
                u4.z = f2tf(vals[i + 2]); u4.w = f2tf(vals[i + 3]);
                *(uint4*)&prow[i] = u4;
            }
        }
        __syncthreads();

        // ---- O = O*corr + P @ V (tensor)
        const float c0v = rowc[wr * 16 + g];
        const float c1v = rowc[wr * 16 + g + 8];
#pragma unroll
        for (int nf = 0; nf < 4; nf++) {
            o[nf][0] *= c0v; o[nf][1] *= c0v;
            o[nf][2] *= c1v; o[nf][3] *= c1v;
        }
#pragma unroll
        for (int ks = 0; ks < 8; ks++) {
            const int kk = ks * 8 + t;
            unsigned a[4];
            const int abase = (wr * 16 + g) * QSTR + kk;
            a[0] = Ps[abase];
            a[1] = Ps[abase + 8 * QSTR];
            a[2] = Ps[abase + 4];
            a[3] = Ps[abase + 8 * QSTR + 4];
#pragma unroll
            for (int nf = 0; nf < 4; nf++) {
                unsigned b[2];
                const int bbase = kk * KSTR + wc * 32 + nf * 8 + g;
                b[0] = Vs[bbase];
                b[1] = Vs[bbase + 4 * KSTR];
                mma8(o[nf], a, b);
            }
        }
        __syncthreads();   // protect Ks/Vs/Ps before next tile load
    }

    // ---- epilogue: normalize, write g_Y in [B*T, C]
    const int b = bh / NH;
    const int h = bh % NH;
    const float l0 = 1.f / rowl[wr * 16 + g];
    const float l1 = 1.f / rowl[wr * 16 + g + 8];
    const int r0 = qt * 64 + wr * 16 + g;
#pragma unroll
    for (int nf = 0; nf < 4; nf++) {
        const int c0 = wc * 32 + nf * 8 + 2 * t;
        float* d0 = g_Y + (size_t)(b * TSEQ + r0) * CDIM + h * 64 + c0;
        *(float2*)d0 = make_float2(o[nf][0] * l0, o[nf][1] * l0);
        float* d1 = g_Y + (size_t)(b * TSEQ + r0 + 8) * CDIM + h * 64 + c0;
        *(float2*)d1 = make_float2(o[nf][2] * l1, o[nf][3] * l1);
    }
}

// ---------------------------------------------------------------------------
// Kernel 3: projection GEMM (tensor core tf32)
// g_Y[8192,768] @ Wproj[768,768] + bias -> out
// ---------------------------------------------------------------------------
__global__ __launch_bounds__(256) void proj_gemm_tc(const float* __restrict__ W,
                                                    const float* __restrict__ bias,
                                                    float* __restrict__ out)
{
    __shared__ unsigned As[32 * GSTR];
    __shared__ unsigned Bs[32 * GSTR];

    const int tid = (int)threadIdx.x;
    const int lane = tid & 31;
    const int wid = tid >> 5;
    const int g = lane >> 2;
    const int t = lane & 3;
    const int m0 = blockIdx.y * 128;
    const int n0 = blockIdx.x * 128;
    const int m0w = (wid & 1) * 64;
    const int n0w = (wid >> 1) * 32;

    const float* A = g_Y;

    float acc[4][4][4];
#pragma unroll
    for (int i = 0; i < 4; i++)
#pragma unroll
        for (int j = 0; j < 4; j++)
#pragma unroll
            for (int k = 0; k < 4; k++) acc[i][j][k] = 0.f;

    for (int kb = 0; kb < CDIM; kb += 32) {
#pragma unroll
        for (int fi = 0; fi < 4; fi++) {
            const int u = fi * 256 + tid;
            const int row = u >> 3;
            const int kc = (u & 7) * 4;
            float4 v = *(const float4*)(A + (size_t)(m0 + row) * CDIM + kb + kc);
            As[(kc + 0) * GSTR + row] = f2tf(v.x);
            As[(kc + 1) * GSTR + row] = f2tf(v.y);
            As[(kc + 2) * GSTR + row] = f2tf(v.z);
            As[(kc + 3) * GSTR + row] = f2tf(v.w);
        }
#pragma unroll
        for (int fi = 0; fi < 4; fi++) {
            const int u = fi * 256 + tid;
            const int row = u >> 5;
            const int nc = (u & 31) * 4;
            float4 v = *(const float4*)(W + (size_t)(kb + row) * CDIM + n0 + nc);
            unsigned* dst = &Bs[row * GSTR + nc];
            dst[0] = f2tf(v.x); dst[1] = f2tf(v.y);
            dst[2] = f2tf(v.z); dst[3] = f2tf(v.w);
        }
        __syncthreads();

#pragma unroll
        for (int ks = 0; ks < 4; ks++) {
            const int kk = ks * 8 + t;
            unsigned a[4][4], b[4][2];
#pragma unroll
            for (int mf = 0; mf < 4; mf++) {
                const int base = kk * GSTR + m0w + mf * 16 + g;
                a[mf][0] = As[base];
                a[mf][1] = As[base + 8];
                a[mf][2] = As[base + 4 * GSTR];
                a[mf][3] = As[base + 4 * GSTR + 8];
            }
#pragma unroll
            for (int nf = 0; nf < 4; nf++) {
                const int base = kk * GSTR + n0w + nf * 8 + g;
                b[nf][0] = Bs[base];
                b[nf][1] = Bs[base + 4 * GSTR];
            }
#pragma unroll
            for (int mf = 0; mf < 4; mf++)
#pragma unroll
                for (int nf = 0; nf < 4; nf++) mma8(acc[mf][nf], a[mf], b[nf]);
        }
        __syncthreads();
    }

#pragma unroll
    for (int mf = 0; mf < 4; mf++) {
        const int r0 = m0 + m0w + mf * 16 + g;
#pragma unroll
        for (int nf = 0; nf < 4; nf++) {
            const int c0 = n0 + n0w + nf * 8 + 2 * t;
            const float b0 = bias[c0], b1 = bias[c0 + 1];
            *(float2*)&out[(size_t)r0 * CDIM + c0] =
                make_float2(acc[mf][nf][0] + b0, acc[mf][nf][1] + b1);
            *(float2*)&out[(size_t)(r0 + 8) * CDIM + c0] =
                make_float2(acc[mf][nf][2] + b0, acc[mf][nf][3] + b1);
        }
    }
}

// ---------------------------------------------------------------------------
extern "C" void kernel_launch(void* const* d_in, const int* in_sizes, int n_in,
                              void* d_out, int out_size)
{
    const float* x     = (const float*)d_in[0];
    const float* Wqkv  = (const float*)d_in[1];
    const float* bqkv  = (const float*)d_in[2];
    const float* Wproj = (const float*)d_in[3];
    const float* bproj = (const float*)d_in[4];
    float* out = (float*)d_out;

    const size_t attn_smem =
        (64 * QSTR /*Q*/ + 64 * KSTR /*K*/ + 64 * KSTR /*V*/ + 64 * QSTR /*S/P*/ + 3 * 64) *
        sizeof(float);  // ~72.4 KB
    cudaFuncSetAttribute(attn_tc, cudaFuncAttributeMaxDynamicSharedMemorySize,
                         (int)attn_smem);

    qkv_gemm_tc<<<dim3(NQKV / 128, MTOK / 128), 256>>>(x, Wqkv, bqkv);
    attn_tc<<<dim3(TSEQ / 64, BH), 256, attn_smem>>>();
    proj_gemm_tc<<<dim3(CDIM / 128, MTOK / 128), 256>>>(Wproj, bproj, out);
}

// round 3
// speedup vs baseline: 4.0010x; 1.8751x over previous
#include <cuda_runtime.h>
#include <cuda_fp16.h>
#include <math.h>

#define BSZ 2
#define TSEQ 4096
#define CDIM 768
#define NH 12
#define HD 64
#define MTOK (BSZ * TSEQ)      // 8192
#define NQKV (3 * CDIM)        // 2304
#define BH (BSZ * NH)          // 24

// Scratch (allocation-free rule: device globals)
__device__ float g_Q[(size_t)BH * TSEQ * HD];   // [b*H+h, T, D]
__device__ float g_K[(size_t)BH * TSEQ * HD];
__device__ float g_V[(size_t)BH * TSEQ * HD];
__device__ float g_Y[(size_t)MTOK * CDIM];      // attention out, [B*T, C]

// ---------------------------------------------------------------------------
// helpers
// ---------------------------------------------------------------------------
__device__ __forceinline__ unsigned f2tf(float f) {
    unsigned r;
    asm("cvt.rna.tf32.f32 %0, %1;" : "=r"(r) : "f"(f));
    return r;
}
__device__ __forceinline__ void mma8(float* c, const unsigned* a, const unsigned* b) {
    asm volatile(
        "mma.sync.aligned.m16n8k8.row.col.f32.tf32.tf32.f32 "
        "{%0,%1,%2,%3}, {%4,%5,%6,%7}, {%8,%9}, {%0,%1,%2,%3};"
        : "+f"(c[0]), "+f"(c[1]), "+f"(c[2]), "+f"(c[3])
        : "r"(a[0]), "r"(a[1]), "r"(a[2]), "r"(a[3]), "r"(b[0]), "r"(b[1]));
}
__device__ __forceinline__ void mma16(float* c, const unsigned* a, unsigned b0, unsigned b1) {
    asm volatile(
        "mma.sync.aligned.m16n8k16.row.col.f32.f16.f16.f32 "
        "{%0,%1,%2,%3}, {%4,%5,%6,%7}, {%8,%9}, {%0,%1,%2,%3};"
        : "+f"(c[0]), "+f"(c[1]), "+f"(c[2]), "+f"(c[3])
        : "r"(a[0]), "r"(a[1]), "r"(a[2]), "r"(a[3]), "r"(b0), "r"(b1));
}
__device__ __forceinline__ void ldsm4(unsigned addr, unsigned& r0, unsigned& r1,
                                      unsigned& r2, unsigned& r3) {
    asm volatile("ldmatrix.sync.aligned.m8n8.x4.shared.b16 {%0,%1,%2,%3}, [%4];"
                 : "=r"(r0), "=r"(r1), "=r"(r2), "=r"(r3) : "r"(addr));
}
__device__ __forceinline__ void ldsm4t(unsigned addr, unsigned& r0, unsigned& r1,
                                       unsigned& r2, unsigned& r3) {
    asm volatile("ldmatrix.sync.aligned.m8n8.x4.trans.shared.b16 {%0,%1,%2,%3}, [%4];"
                 : "=r"(r0), "=r"(r1), "=r"(r2), "=r"(r3) : "r"(addr));
}
__device__ __forceinline__ float ex2(float x) {
    float r;
    asm("ex2.approx.f32 %0, %1;" : "=f"(r) : "f"(x));
    return r;
}
__device__ __forceinline__ unsigned packh2(float a, float b) {
    __half2 h = __floats2half2_rn(a, b);
    return *(unsigned*)&h;
}

// ---------------------------------------------------------------------------
// Kernel 1: QKV GEMM (tf32, unchanged from R2)
// ---------------------------------------------------------------------------
#define GSTR 136

__device__ __forceinline__ void scatter_qkv2(int m, int n, float v0, float v1) {
    const int b = m >> 12;
    const int tt = m & 4095;
    const int sel = n / CDIM;
    const int r = n - sel * CDIM;
    const int h = r >> 6;
    const int d = r & 63;
    float* dst = (sel == 0) ? g_Q : ((sel == 1) ? g_K : g_V);
    *(float2*)&dst[((size_t)(b * NH + h) * TSEQ + tt) * HD + d] = make_float2(v0, v1);
}

__global__ __launch_bounds__(256) void qkv_gemm_tc(const float* __restrict__ A,
                                                   const float* __restrict__ W,
                                                   const float* __restrict__ bias)
{
    __shared__ unsigned As[32 * GSTR];
    __shared__ unsigned Bs[32 * GSTR];

    const int tid = (int)threadIdx.x;
    const int lane = tid & 31;
    const int wid = tid >> 5;
    const int g = lane >> 2;
    const int t = lane & 3;
    const int m0 = blockIdx.y * 128;
    const int n0 = blockIdx.x * 128;
    const int m0w = (wid & 1) * 64;
    const int n0w = (wid >> 1) * 32;

    float acc[4][4][4];
#pragma unroll
    for (int i = 0; i < 4; i++)
#pragma unroll
        for (int j = 0; j < 4; j++)
#pragma unroll
            for (int k = 0; k < 4; k++) acc[i][j][k] = 0.f;

    for (int kb = 0; kb < CDIM; kb += 32) {
#pragma unroll
        for (int fi = 0; fi < 4; fi++) {
            const int u = fi * 256 + tid;
            const int row = u >> 3;
            const int kc = (u & 7) * 4;
            float4 v = *(const float4*)(A + (size_t)(m0 + row) * CDIM + kb + kc);
            As[(kc + 0) * GSTR + row] = f2tf(v.x);
            As[(kc + 1) * GSTR + row] = f2tf(v.y);
            As[(kc + 2) * GSTR + row] = f2tf(v.z);
            As[(kc + 3) * GSTR + row] = f2tf(v.w);
        }
#pragma unroll
        for (int fi = 0; fi < 4; fi++) {
            const int u = fi * 256 + tid;
            const int row = u >> 5;
            const int nc = (u & 31) * 4;
            float4 v = *(const float4*)(W + (size_t)(kb + row) * NQKV + n0 + nc);
            unsigned* dst = &Bs[row * GSTR + nc];
            dst[0] = f2tf(v.x); dst[1] = f2tf(v.y);
            dst[2] = f2tf(v.z); dst[3] = f2tf(v.w);
        }
        __syncthreads();

#pragma unroll
        for (int ks = 0; ks < 4; ks++) {
            const int kk = ks * 8 + t;
            unsigned a[4][4], b[4][2];
#pragma unroll
            for (int mf = 0; mf < 4; mf++) {
                const int base = kk * GSTR + m0w + mf * 16 + g;
                a[mf][0] = As[base];
                a[mf][1] = As[base + 8];
                a[mf][2] = As[base + 4 * GSTR];
                a[mf][3] = As[base + 4 * GSTR + 8];
            }
#pragma unroll
            for (int nf = 0; nf < 4; nf++) {
                const int base = kk * GSTR + n0w + nf * 8 + g;
                b[nf][0] = Bs[base];
                b[nf][1] = Bs[base + 4 * GSTR];
            }
#pragma unroll
            for (int mf = 0; mf < 4; mf++)
#pragma unroll
                for (int nf = 0; nf < 4; nf++) mma8(acc[mf][nf], a[mf], b[nf]);
        }
        __syncthreads();
    }

#pragma unroll
    for (int mf = 0; mf < 4; mf++) {
        const int r0 = m0 + m0w + mf * 16 + g;
#pragma unroll
        for (int nf = 0; nf < 4; nf++) {
            const int c0 = n0 + n0w + nf * 8 + 2 * t;
            const float b0 = bias[c0], b1 = bias[c0 + 1];
            scatter_qkv2(r0,     c0, acc[mf][nf][0] + b0, acc[mf][nf][1] + b1);
            scatter_qkv2(r0 + 8, c0, acc[mf][nf][2] + b0, acc[mf][nf][3] + b1);
        }
    }
}

// ---------------------------------------------------------------------------
// Kernel 2: causal flash attention, fp16 mma, register-resident S/P/O.
// Block = 128 q-rows x 64 kv. 8 warps, warp = 16 q-rows x full 64 kv width.
// ---------------------------------------------------------------------------
#define KVSTR 72   // half stride (144 B) -> ldmatrix conflict-free

__global__ __launch_bounds__(256) void attn_fa16()
{
    __shared__ __half sm[2 * 64 * KVSTR];    // 18432 B; also Q staging [128][KVSTR]
    __half* Ksm = sm;
    __half* Vsm = sm + 64 * KVSTR;

    const int qt  = (int)gridDim.x - 1 - (int)blockIdx.x;  // heavy blocks first
    const int bh  = (int)blockIdx.y;
    const int tid = (int)threadIdx.x;
    const int lane = tid & 31;
    const int wid  = tid >> 5;
    const int g = lane >> 2;
    const int t = lane & 3;

    const float* Qg = g_Q + (size_t)bh * TSEQ * HD + (size_t)qt * 128 * HD;
    const float* Kg = g_K + (size_t)bh * TSEQ * HD;
    const float* Vg = g_V + (size_t)bh * TSEQ * HD;

    const float qs = 0.125f * 1.4426950408889634f;   // 1/sqrt(D) * log2(e)

    // ---- stage Q (fp32 -> half) into smem
    {
        const int r = tid >> 1;
        const int c0 = (tid & 1) * 32;
        const float* src = Qg + r * 64 + c0;
        __half* dst = sm + r * KVSTR + c0;
#pragma unroll
        for (int v = 0; v < 4; v++) {
            float4 f0 = *(const float4*)(src + v * 8);
            float4 f1 = *(const float4*)(src + v * 8 + 4);
            uint4 u;
            u.x = packh2(f0.x * qs, f0.y * qs);
            u.y = packh2(f0.z * qs, f0.w * qs);
            u.z = packh2(f1.x * qs, f1.y * qs);
            u.w = packh2(f1.z * qs, f1.w * qs);
            *(uint4*)(dst + v * 8) = u;
        }
    }
    __syncthreads();

    // ---- Q fragments to registers (warp rows wid*16 .. +15)
    unsigned qf[4][4];
    {
        const unsigned base = (unsigned)__cvta_generic_to_shared(sm);
        const int qrow = wid * 16 + (lane & 15);
        const int koff = (lane & 16) ? 8 : 0;
#pragma unroll
        for (int ks = 0; ks < 4; ks++)
            ldsm4(base + (unsigned)(qrow * KVSTR + ks * 16 + koff) * 2u,
                  qf[ks][0], qf[ks][1], qf[ks][2], qf[ks][3]);
    }
    __syncthreads();   // Q buffer now reusable for K/V

    float of[8][4];
#pragma unroll
    for (int i = 0; i < 8; i++)
#pragma unroll
        for (int j = 0; j < 4; j++) of[i][j] = 0.f;
    float m0 = -1e30f, m1 = -1e30f, l0 = 0.f, l1 = 0.f;

    const unsigned kb = (unsigned)__cvta_generic_to_shared(Ksm);
    const unsigned vb = (unsigned)__cvta_generic_to_shared(Vsm);
    const int r0 = qt * 128 + wid * 16 + g;
    const int r1 = r0 + 8;
    const int ntiles = 2 * qt + 2;

    for (int jt = 0; jt < ntiles; jt++) {
        // ---- load K,V tiles (64x64 fp32 -> half)
        {
            const int r = tid >> 2;
            const int c0 = (tid & 3) * 16;
            const float* ks = Kg + (size_t)(jt * 64 + r) * 64 + c0;
            const float* vs = Vg + (size_t)(jt * 64 + r) * 64 + c0;
            __half* kd = Ksm + r * KVSTR + c0;
            __half* vd = Vsm + r * KVSTR + c0;
#pragma unroll
            for (int v = 0; v < 2; v++) {
                float4 a0 = *(const float4*)(ks + v * 8);
                float4 a1 = *(const float4*)(ks + v * 8 + 4);
                uint4 u;
                u.x = packh2(a0.x, a0.y); u.y = packh2(a0.z, a0.w);
                u.z = packh2(a1.x, a1.y); u.w = packh2(a1.z, a1.w);
                *(uint4*)(kd + v * 8) = u;
                float4 b0 = *(const float4*)(vs + v * 8);
                float4 b1 = *(const float4*)(vs + v * 8 + 4);
                uint4 w;
                w.x = packh2(b0.x, b0.y); w.y = packh2(b0.z, b0.w);
                w.z = packh2(b1.x, b1.y); w.w = packh2(b1.z, b1.w);
                *(uint4*)(vd + v * 8) = w;
            }
        }
        __syncthreads();

        // ---- S = Q K^T (in log2 domain; Q pre-scaled)
        float s[8][4];
#pragma unroll
        for (int i = 0; i < 8; i++)
#pragma unroll
            for (int j = 0; j < 4; j++) s[i][j] = 0.f;

        {
            const int nrow = (lane & 7);
            const int kc = ((lane >> 3) & 3) * 8;
#pragma unroll
            for (int nf = 0; nf < 8; nf++) {
                unsigned b0, b1, b2, b3;
                ldsm4(kb + (unsigned)((nf * 8 + nrow) * KVSTR + kc) * 2u, b0, b1, b2, b3);
                mma16(s[nf], qf[0], b0, b1);
                mma16(s[nf], qf[1], b2, b3);
                ldsm4(kb + (unsigned)((nf * 8 + nrow) * KVSTR + 32 + kc) * 2u, b0, b1, b2, b3);
                mma16(s[nf], qf[2], b0, b1);
                mma16(s[nf], qf[3], b2, b3);
            }
        }

        // ---- causal mask (warp-uniform skip when tile fully below diagonal)
        if (jt * 64 + 63 > qt * 128 + wid * 16) {
#pragma unroll
            for (int nf = 0; nf < 8; nf++) {
                const int c = jt * 64 + nf * 8 + 2 * t;
                if (c > r0)     s[nf][0] = -1e30f;
                if (c + 1 > r0) s[nf][1] = -1e30f;
                if (c > r1)     s[nf][2] = -1e30f;
                if (c + 1 > r1) s[nf][3] = -1e30f;
            }
        }

        // ---- online softmax (register, quad shuffles)
        float mx0 = -1e30f, mx1 = -1e30f;
#pragma unroll
        for (int nf = 0; nf < 8; nf++) {
            mx0 = fmaxf(mx0, fmaxf(s[nf][0], s[nf][1]));
            mx1 = fmaxf(mx1, fmaxf(s[nf][2], s[nf][3]));
        }
        mx0 = fmaxf(mx0, __shfl_xor_sync(0xffffffffu, mx0, 1));
        mx0 = fmaxf(mx0, __shfl_xor_sync(0xffffffffu, mx0, 2));
        mx1 = fmaxf(mx1, __shfl_xor_sync(0xffffffffu, mx1, 1));
        mx1 = fmaxf(mx1, __shfl_xor_sync(0xffffffffu, mx1, 2));

        const float nm0 = fmaxf(m0, mx0);
        const float nm1 = fmaxf(m1, mx1);
        const float cr0 = ex2(m0 - nm0);
        const float cr1 = ex2(m1 - nm1);
        m0 = nm0; m1 = nm1;

        float ls0 = 0.f, ls1 = 0.f;
#pragma unroll
        for (int nf = 0; nf < 8; nf++) {
            s[nf][0] = ex2(s[nf][0] - nm0);
            s[nf][1] = ex2(s[nf][1] - nm0);
            s[nf][2] = ex2(s[nf][2] - nm1);
            s[nf][3] = ex2(s[nf][3] - nm1);
            ls0 += s[nf][0] + s[nf][1];
            ls1 += s[nf][2] + s[nf][3];
        }
        ls0 += __shfl_xor_sync(0xffffffffu, ls0, 1);
        ls0 += __shfl_xor_sync(0xffffffffu, ls0, 2);
        ls1 += __shfl_xor_sync(0xffffffffu, ls1, 1);
        ls1 += __shfl_xor_sync(0xffffffffu, ls1, 2);
        l0 = l0 * cr0 + ls0;
        l1 = l1 * cr1 + ls1;

#pragma unroll
        for (int df = 0; df < 8; df++) {
            of[df][0] *= cr0; of[df][1] *= cr0;
            of[df][2] *= cr1; of[df][3] *= cr1;
        }

        // ---- P -> fp16 A-fragments (register repack, no smem)
        unsigned pf[4][4];
#pragma unroll
        for (int kc = 0; kc < 4; kc++) {
            pf[kc][0] = packh2(s[2 * kc][0],     s[2 * kc][1]);
            pf[kc][1] = packh2(s[2 * kc][2],     s[2 * kc][3]);
            pf[kc][2] = packh2(s[2 * kc + 1][0], s[2 * kc + 1][1]);
            pf[kc][3] = packh2(s[2 * kc + 1][2], s[2 * kc + 1][3]);
        }

        // ---- O += P V
        {
            const int vrow = (lane & 7) + ((lane >> 3) & 3) * 8;   // kv 0..31
#pragma unroll
            for (int df = 0; df < 8; df++) {
                unsigned b0, b1, b2, b3;
                ldsm4t(vb + (unsigned)(vrow * KVSTR + df * 8) * 2u, b0, b1, b2, b3);
                mma16(of[df], pf[0], b0, b1);
                mma16(of[df], pf[1], b2, b3);
                ldsm4t(vb + (unsigned)((vrow + 32) * KVSTR + df * 8) * 2u, b0, b1, b2, b3);
                mma16(of[df], pf[2], b0, b1);
                mma16(of[df], pf[3], b2, b3);
            }
        }
        __syncthreads();   // protect K/V before next load
    }

    // ---- epilogue
    const int b = bh / NH;
    const int h = bh % NH;
    const float il0 = 1.f / l0;
    const float il1 = 1.f / l1;
#pragma unroll
    for (int df = 0; df < 8; df++) {
        const int col = h * 64 + df * 8 + 2 * t;
        *(float2*)&g_Y[(size_t)(b * TSEQ + r0) * CDIM + col] =
            make_float2(of[df][0] * il0, of[df][1] * il0);
        *(float2*)&g_Y[(size_t)(b * TSEQ + r1) * CDIM + col] =
            make_float2(of[df][2] * il1, of[df][3] * il1);
    }
}

// ---------------------------------------------------------------------------
// Kernel 3: projection GEMM (tf32, unchanged from R2)
// ---------------------------------------------------------------------------
__global__ __launch_bounds__(256) void proj_gemm_tc(const float* __restrict__ W,
                                                    const float* __restrict__ bias,
                                                    float* __restrict__ out)
{
    __shared__ unsigned As[32 * GSTR];
    __shared__ unsigned Bs[32 * GSTR];

    const int tid = (int)threadIdx.x;
    const int lane = tid & 31;
    const int wid = tid >> 5;
    const int g = lane >> 2;
    const int t = lane & 3;
    const int m0 = blockIdx.y * 128;
    const int n0 = blockIdx.x * 128;
    const int m0w = (wid & 1) * 64;
    const int n0w = (wid >> 1) * 32;

    const float* A = g_Y;

    float acc[4][4][4];
#pragma unroll
    for (int i = 0; i < 4; i++)
#pragma unroll
        for (int j = 0; j < 4; j++)
#pragma unroll
            for (int k = 0; k < 4; k++) acc[i][j][k] = 0.f;

    for (int kb = 0; kb < CDIM; kb += 32) {
#pragma unroll
        for (int fi = 0; fi < 4; fi++) {
            const int u = fi * 256 + tid;
            const int row = u >> 3;
            const int kc = (u & 7) * 4;
            float4 v = *(const float4*)(A + (size_t)(m0 + row) * CDIM + kb + kc);
            As[(kc + 0) * GSTR + row] = f2tf(v.x);
            As[(kc + 1) * GSTR + row] = f2tf(v.y);
            As[(kc + 2) * GSTR + row] = f2tf(v.z);
            As[(kc + 3) * GSTR + row] = f2tf(v.w);
        }
#pragma unroll
        for (int fi = 0; fi < 4; fi++) {
            const int u = fi * 256 + tid;
            const int row = u >> 5;
            const int nc = (u & 31) * 4;
            float4 v = *(const float4*)(W + (size_t)(kb + row) * CDIM + n0 + nc);
            unsigned* dst = &Bs[row * GSTR + nc];
            dst[0] = f2tf(v.x); dst[1] = f2tf(v.y);
            dst[2] = f2tf(v.z); dst[3] = f2tf(v.w);
        }
        __syncthreads();

#pragma unroll
        for (int ks = 0; ks < 4; ks++) {
            const int kk = ks * 8 + t;
            unsigned a[4][4], b[4][2];
#pragma unroll
            for (int mf = 0; mf < 4; mf++) {
                const int base = kk * GSTR + m0w + mf * 16 + g;
                a[mf][0] = As[base];
                a[mf][1] = As[base + 8];
                a[mf][2] = As[base + 4 * GSTR];
                a[mf][3] = As[base + 4 * GSTR + 8];
            }
#pragma unroll
            for (int nf = 0; nf < 4; nf++) {
                const int base = kk * GSTR + n0w + nf * 8 + g;
                b[nf][0] = Bs[base];
                b[nf][1] = Bs[base + 4 * GSTR];
            }
#pragma unroll
            for (int mf = 0; mf < 4; mf++)
#pragma unroll
                for (int nf = 0; nf < 4; nf++) mma8(acc[mf][nf], a[mf], b[nf]);
        }
        __syncthreads();
    }

#pragma unroll
    for (int mf = 0; mf < 4; mf++) {
        const int r0 = m0 + m0w + mf * 16 + g;
#pragma unroll
        for (int nf = 0; nf < 4; nf++) {
            const int c0 = n0 + n0w + nf * 8 + 2 * t;
            const float b0 = bias[c0], b1 = bias[c0 + 1];
            *(float2*)&out[(size_t)r0 * CDIM + c0] =
                make_float2(acc[mf][nf][0] + b0, acc[mf][nf][1] + b1);
            *(float2*)&out[(size_t)(r0 + 8) * CDIM + c0] =
                make_float2(acc[mf][nf][2] + b0, acc[mf][nf][3] + b1);
        }
    }
}

// ---------------------------------------------------------------------------
extern "C" void kernel_launch(void* const* d_in, const int* in_sizes, int n_in,
                              void* d_out, int out_size)
{
    const float* x     = (const float*)d_in[0];
    const float* Wqkv  = (const float*)d_in[1];
    const float* bqkv  = (const float*)d_in[2];
    const float* Wproj = (const float*)d_in[3];
    const float* bproj = (const float*)d_in[4];
    float* out = (float*)d_out;

    qkv_gemm_tc<<<dim3(NQKV / 128, MTOK / 128), 256>>>(x, Wqkv, bqkv);
    attn_fa16<<<dim3(TSEQ / 128, BH), 256>>>();
    proj_gemm_tc<<<dim3(CDIM / 128, MTOK / 128), 256>>>(Wproj, bproj, out);
}

// round 4
// speedup vs baseline: 4.7070x; 1.1765x over previous
#include <cuda_runtime.h>
#include <cuda_fp16.h>
#include <math.h>

#define BSZ 2
#define TSEQ 4096
#define CDIM 768
#define NH 12
#define HD 64
#define MTOK (BSZ * TSEQ)      // 8192
#define NQKV (3 * CDIM)        // 2304
#define BH (BSZ * NH)          // 24

// Scratch (allocation-free rule: device globals) — all fp16 now
__device__ __half g_Q[(size_t)BH * TSEQ * HD];   // [b*H+h, T, D], pre-scaled by qs
__device__ __half g_K[(size_t)BH * TSEQ * HD];
__device__ __half g_V[(size_t)BH * TSEQ * HD];
__device__ __half g_Y[(size_t)MTOK * CDIM];      // attention out, [B*T, C]

// ---------------------------------------------------------------------------
// helpers
// ---------------------------------------------------------------------------
__device__ __forceinline__ void mma16(float* c, const unsigned* a, unsigned b0, unsigned b1) {
    asm volatile(
        "mma.sync.aligned.m16n8k16.row.col.f32.f16.f16.f32 "
        "{%0,%1,%2,%3}, {%4,%5,%6,%7}, {%8,%9}, {%0,%1,%2,%3};"
        : "+f"(c[0]), "+f"(c[1]), "+f"(c[2]), "+f"(c[3])
        : "r"(a[0]), "r"(a[1]), "r"(a[2]), "r"(a[3]), "r"(b0), "r"(b1));
}
__device__ __forceinline__ void ldsm4(unsigned addr, unsigned& r0, unsigned& r1,
                                      unsigned& r2, unsigned& r3) {
    asm volatile("ldmatrix.sync.aligned.m8n8.x4.shared.b16 {%0,%1,%2,%3}, [%4];"
                 : "=r"(r0), "=r"(r1), "=r"(r2), "=r"(r3) : "r"(addr));
}
__device__ __forceinline__ void ldsm4t(unsigned addr, unsigned& r0, unsigned& r1,
                                       unsigned& r2, unsigned& r3) {
    asm volatile("ldmatrix.sync.aligned.m8n8.x4.trans.shared.b16 {%0,%1,%2,%3}, [%4];"
                 : "=r"(r0), "=r"(r1), "=r"(r2), "=r"(r3) : "r"(addr));
}
__device__ __forceinline__ float ex2(float x) {
    float r;
    asm("ex2.approx.f32 %0, %1;" : "=f"(r) : "f"(x));
    return r;
}
__device__ __forceinline__ unsigned packh2(float a, float b) {
    __half2 h = __floats2half2_rn(a, b);
    return *(unsigned*)&h;
}
// convert 8 consecutive floats to a uint4 of half2s
__device__ __forceinline__ uint4 cvt8(const float* p) {
    float4 f0 = *(const float4*)p;
    float4 f1 = *(const float4*)(p + 4);
    uint4 u;
    u.x = packh2(f0.x, f0.y); u.y = packh2(f0.z, f0.w);
    u.z = packh2(f1.x, f1.y); u.w = packh2(f1.z, f1.w);
    return u;
}

#define QS (0.125f * 1.4426950408889634f)   // 1/sqrt(D) * log2(e)

// ---------------------------------------------------------------------------
// Kernel 1: QKV GEMM (fp16 mma + ldmatrix)
// x[8192,768] @ Wqkv[768,2304] + bias -> scatter head-major Q(scaled)/K/V fp16.
// 128x128x64 tile, 256 threads (8 warps, warp tile 64x32).
// ---------------------------------------------------------------------------
#define ASTR 72    // A smem stride (halves): 64+8
#define BSTR 136   // B smem stride (halves): 128+8

__device__ __forceinline__ void scatter_qkv2(int m, int n, float v0, float v1) {
    const int b = m >> 12;
    const int tt = m & 4095;
    const int sel = n / CDIM;            // 0=Q,1=K,2=V
    const int r = n - sel * CDIM;
    const int h = r >> 6;
    const int d = r & 63;
    if (sel == 0) { v0 *= QS; v1 *= QS; }
    __half* dst = (sel == 0) ? g_Q : ((sel == 1) ? g_K : g_V);
    *(__half2*)&dst[((size_t)(b * NH + h) * TSEQ + tt) * HD + d] = __floats2half2_rn(v0, v1);
}

__global__ __launch_bounds__(256) void qkv_gemm_f16(const float* __restrict__ A,
                                                    const float* __restrict__ W,
                                                    const float* __restrict__ bias)
{
    __shared__ __half As[128 * ASTR];   // [m][k], 18 KB
    __shared__ __half Bs[64 * BSTR];    // [k][n], 17.4 KB

    const int tid = (int)threadIdx.x;
    const int lane = tid & 31;
    const int wid = tid >> 5;
    const int g = lane >> 2;
    const int t = lane & 3;
    const int m0 = blockIdx.y * 128;
    const int n0 = blockIdx.x * 128;
    const int m0w = (wid & 1) * 64;
    const int n0w = (wid >> 1) * 32;

    const unsigned asb = (unsigned)__cvta_generic_to_shared(As);
    const unsigned bsb = (unsigned)__cvta_generic_to_shared(Bs);

    float acc[4][4][4];
#pragma unroll
    for (int i = 0; i < 4; i++)
#pragma unroll
        for (int j = 0; j < 4; j++)
#pragma unroll
            for (int k = 0; k < 4; k++) acc[i][j][k] = 0.f;

    const int ar = tid >> 1, ac = (tid & 1) * 32;
    const int br = tid >> 2, bc = (tid & 3) * 32;
    const int arow = lane & 15;
    const int koff = (lane & 16) ? 8 : 0;
    const int trow = (lane & 7) + ((lane >> 3) & 3) * 8;   // 0..31 within 32-k chunk

    for (int kb = 0; kb < CDIM; kb += 64) {
        // A tile 128x64 fp32 -> fp16
        {
            const float* src = A + (size_t)(m0 + ar) * CDIM + kb + ac;
            __half* dst = As + ar * ASTR + ac;
#pragma unroll
            for (int v = 0; v < 4; v++) *(uint4*)(dst + v * 8) = cvt8(src + v * 8);
        }
        // B tile 64x128 fp32 -> fp16
        {
            const float* src = W + (size_t)(kb + br) * NQKV + n0 + bc;
            __half* dst = Bs + br * BSTR + bc;
#pragma unroll
            for (int v = 0; v < 4; v++) *(uint4*)(dst + v * 8) = cvt8(src + v * 8);
        }
        __syncthreads();

#pragma unroll
        for (int kc = 0; kc < 2; kc++) {   // two 32-k chunks
            unsigned af[2][4][4], bb[4][4];
#pragma unroll
            for (int mf = 0; mf < 4; mf++) {
                const unsigned base = asb +
                    (unsigned)((m0w + mf * 16 + arow) * ASTR + kc * 32 + koff) * 2u;
                ldsm4(base,      af[0][mf][0], af[0][mf][1], af[0][mf][2], af[0][mf][3]);
                ldsm4(base + 32, af[1][mf][0], af[1][mf][1], af[1][mf][2], af[1][mf][3]);
            }
#pragma unroll
            for (int nf = 0; nf < 4; nf++) {
                ldsm4t(bsb + (unsigned)((kc * 32 + trow) * BSTR + n0w + nf * 8) * 2u,
                       bb[nf][0], bb[nf][1], bb[nf][2], bb[nf][3]);
            }
#pragma unroll
            for (int mf = 0; mf < 4; mf++)
#pragma unroll
                for (int nf = 0; nf < 4; nf++) {
                    mma16(acc[mf][nf], af[0][mf], bb[nf][0], bb[nf][1]);
                    mma16(acc[mf][nf], af[1][mf], bb[nf][2], bb[nf][3]);
                }
        }
        __syncthreads();
    }

#pragma unroll
    for (int mf = 0; mf < 4; mf++) {
        const int r0 = m0 + m0w + mf * 16 + g;
#pragma unroll
        for (int nf = 0; nf < 4; nf++) {
            const int c0 = n0 + n0w + nf * 8 + 2 * t;
            const float b0 = bias[c0], b1 = bias[c0 + 1];
            scatter_qkv2(r0,     c0, acc[mf][nf][0] + b0, acc[mf][nf][1] + b1);
            scatter_qkv2(r0 + 8, c0, acc[mf][nf][2] + b0, acc[mf][nf][3] + b1);
        }
    }
}

// ---------------------------------------------------------------------------
// Kernel 2: causal flash attention, fp16 mma, register-resident S/P/O.
// Q/K/V already fp16 (Q pre-scaled). Block = 128 q x 64 kv, 8 warps.
// ---------------------------------------------------------------------------
#define KVSTR 72

__global__ __launch_bounds__(256) void attn_fa16()
{
    __shared__ __half sm[2 * 64 * KVSTR];    // 18 KB; also Q staging [128][KVSTR]
    __half* Ksm = sm;
    __half* Vsm = sm + 64 * KVSTR;

    const int qt  = (int)gridDim.x - 1 - (int)blockIdx.x;
    const int bh  = (int)blockIdx.y;
    const int tid = (int)threadIdx.x;
    const int lane = tid & 31;
    const int wid  = tid >> 5;
    const int g = lane >> 2;
    const int t = lane & 3;

    const __half* Qg = g_Q + (size_t)bh * TSEQ * HD + (size_t)qt * 128 * HD;
    const __half* Kg = g_K + (size_t)bh * TSEQ * HD;
    const __half* Vg = g_V + (size_t)bh * TSEQ * HD;

    // ---- stage Q (pure copy, already scaled fp16)
    {
        const int r = tid >> 1;
        const int c0 = (tid & 1) * 32;
        const __half* src = Qg + r * 64 + c0;
        __half* dst = sm + r * KVSTR + c0;
#pragma unroll
        for (int v = 0; v < 4; v++) *(uint4*)(dst + v * 8) = *(const uint4*)(src + v * 8);
    }
    __syncthreads();

    unsigned qf[4][4];
    {
        const unsigned base = (unsigned)__cvta_generic_to_shared(sm);
        const int qrow = wid * 16 + (lane & 15);
        const int koff = (lane & 16) ? 8 : 0;
#pragma unroll
        for (int ks = 0; ks < 4; ks++)
            ldsm4(base + (unsigned)(qrow * KVSTR + ks * 16 + koff) * 2u,
                  qf[ks][0], qf[ks][1], qf[ks][2], qf[ks][3]);
    }
    __syncthreads();

    float of[8][4];
#pragma unroll
    for (int i = 0; i < 8; i++)
#pragma unroll
        for (int j = 0; j < 4; j++) of[i][j] = 0.f;
    float m0 = -1e30f, m1 = -1e30f, l0 = 0.f, l1 = 0.f;

    const unsigned kb = (unsigned)__cvta_generic_to_shared(Ksm);
    const unsigned vb = (unsigned)__cvta_generic_to_shared(Vsm);
    const int r0 = qt * 128 + wid * 16 + g;
    const int r1 = r0 + 8;
    const int ntiles = 2 * qt + 2;

    for (int jt = 0; jt < ntiles; jt++) {
        // ---- load K,V tiles (pure fp16 copies)
        {
            const int r = tid >> 2;
            const int c0 = (tid & 3) * 16;
            const __half* ks = Kg + (size_t)(jt * 64 + r) * 64 + c0;
            const __half* vs = Vg + (size_t)(jt * 64 + r) * 64 + c0;
            __half* kd = Ksm + r * KVSTR + c0;
            __half* vd = Vsm + r * KVSTR + c0;
            *(uint4*)(kd + 0) = *(const uint4*)(ks + 0);
            *(uint4*)(kd + 8) = *(const uint4*)(ks + 8);
            *(uint4*)(vd + 0) = *(const uint4*)(vs + 0);
            *(uint4*)(vd + 8) = *(const uint4*)(vs + 8);
        }
        __syncthreads();

        // ---- S = Q K^T (log2 domain; Q pre-scaled)
        float s[8][4];
#pragma unroll
        for (int i = 0; i < 8; i++)
#pragma unroll
            for (int j = 0; j < 4; j++) s[i][j] = 0.f;

        {
            const int nrow = (lane & 7);
            const int kc = ((lane >> 3) & 3) * 8;
#pragma unroll
            for (int nf = 0; nf < 8; nf++) {
                unsigned b0, b1, b2, b3;
                ldsm4(kb + (unsigned)((nf * 8 + nrow) * KVSTR + kc) * 2u, b0, b1, b2, b3);
                mma16(s[nf], qf[0], b0, b1);
                mma16(s[nf], qf[1], b2, b3);
                ldsm4(kb + (unsigned)((nf * 8 + nrow) * KVSTR + 32 + kc) * 2u, b0, b1, b2, b3);
                mma16(s[nf], qf[2], b0, b1);
                mma16(s[nf], qf[3], b2, b3);
            }
        }

        // ---- causal mask
        if (jt * 64 + 63 > qt * 128 + wid * 16) {
#pragma unroll
            for (int nf = 0; nf < 8; nf++) {
                const int c = jt * 64 + nf * 8 + 2 * t;
                if (c > r0)     s[nf][0] = -1e30f;
                if (c + 1 > r0) s[nf][1] = -1e30f;
                if (c > r1)     s[nf][2] = -1e30f;
                if (c + 1 > r1) s[nf][3] = -1e30f;
            }
        }

        // ---- online softmax (registers + quad shuffles)
        float mx0 = -1e30f, mx1 = -1e30f;
#pragma unroll
        for (int nf = 0; nf < 8; nf++) {
            mx0 = fmaxf(mx0, fmaxf(s[nf][0], s[nf][1]));
            mx1 = fmaxf(mx1, fmaxf(s[nf][2], s[nf][3]));
        }
        mx0 = fmaxf(mx0, __shfl_xor_sync(0xffffffffu, mx0, 1));
        mx0 = fmaxf(mx0, __shfl_xor_sync(0xffffffffu, mx0, 2));
        mx1 = fmaxf(mx1, __shfl_xor_sync(0xffffffffu, mx1, 1));
        mx1 = fmaxf(mx1, __shfl_xor_sync(0xffffffffu, mx1, 2));

        const float nm0 = fmaxf(m0, mx0);
        const float nm1 = fmaxf(m1, mx1);
        const float cr0 = ex2(m0 - nm0);
        const float cr1 = ex2(m1 - nm1);
        m0 = nm0; m1 = nm1;

        float ls0 = 0.f, ls1 = 0.f;
#pragma unroll
        for (int nf = 0; nf < 8; nf++) {
            s[nf][0] = ex2(s[nf][0] - nm0);
            s[nf][1] = ex2(s[nf][1] - nm0);
            s[nf][2] = ex2(s[nf][2] - nm1);
            s[nf][3] = ex2(s[nf][3] - nm1);
            ls0 += s[nf][0] + s[nf][1];
            ls1 += s[nf][2] + s[nf][3];
        }
        ls0 += __shfl_xor_sync(0xffffffffu, ls0, 1);
        ls0 += __shfl_xor_sync(0xffffffffu, ls0, 2);
        ls1 += __shfl_xor_sync(0xffffffffu, ls1, 1);
        ls1 += __shfl_xor_sync(0xffffffffu, ls1, 2);
        l0 = l0 * cr0 + ls0;
        l1 = l1 * cr1 + ls1;

#pragma unroll
        for (int df = 0; df < 8; df++) {
            of[df][0] *= cr0; of[df][1] *= cr0;
            of[df][2] *= cr1; of[df][3] *= cr1;
        }

        // ---- P -> fp16 A-fragments
        unsigned pf[4][4];
#pragma unroll
        for (int kc = 0; kc < 4; kc++) {
            pf[kc][0] = packh2(s[2 * kc][0],     s[2 * kc][1]);
            pf[kc][1] = packh2(s[2 * kc][2],     s[2 * kc][3]);
            pf[kc][2] = packh2(s[2 * kc + 1][0], s[2 * kc + 1][1]);
            pf[kc][3] = packh2(s[2 * kc + 1][2], s[2 * kc + 1][3]);
        }

        // ---- O += P V
        {
            const int vrow = (lane & 7) + ((lane >> 3) & 3) * 8;
#pragma unroll
            for (int df = 0; df < 8; df++) {
                unsigned b0, b1, b2, b3;
                ldsm4t(vb + (unsigned)(vrow * KVSTR + df * 8) * 2u, b0, b1, b2, b3);
                mma16(of[df], pf[0], b0, b1);
                mma16(of[df], pf[1], b2, b3);
                ldsm4t(vb + (unsigned)((vrow + 32) * KVSTR + df * 8) * 2u, b0, b1, b2, b3);
                mma16(of[df], pf[2], b0, b1);
                mma16(of[df], pf[3], b2, b3);
            }
        }
        __syncthreads();
    }

    // ---- epilogue: normalize, write g_Y (fp16) in [B*T, C]
    const int b = bh / NH;
    const int h = bh % NH;
    const float il0 = 1.f / l0;
    const float il1 = 1.f / l1;
#pragma unroll
    for (int df = 0; df < 8; df++) {
        const int col = h * 64 + df * 8 + 2 * t;
        *(__half2*)&g_Y[(size_t)(b * TSEQ + r0) * CDIM + col] =
            __floats2half2_rn(of[df][0] * il0, of[df][1] * il0);
        *(__half2*)&g_Y[(size_t)(b * TSEQ + r1) * CDIM + col] =
            __floats2half2_rn(of[df][2] * il1, of[df][3] * il1);
    }
}

// ---------------------------------------------------------------------------
// Kernel 3: projection GEMM (fp16 mma + ldmatrix)
// g_Y[8192,768] (fp16) @ Wproj[768,768] + bias -> out (fp32)
// ---------------------------------------------------------------------------
__global__ __launch_bounds__(256) void proj_gemm_f16(const float* __restrict__ W,
                                                     const float* __restrict__ bias,
                                                     float* __restrict__ out)
{
    __shared__ __half As[128 * ASTR];
    __shared__ __half Bs[64 * BSTR];

    const int tid = (int)threadIdx.x;
    const int lane = tid & 31;
    const int wid = tid >> 5;
    const int g = lane >> 2;
    const int t = lane & 3;
    const int m0 = blockIdx.y * 128;
    const int n0 = blockIdx.x * 128;
    const int m0w = (wid & 1) * 64;
    const int n0w = (wid >> 1) * 32;

    const unsigned asb = (unsigned)__cvta_generic_to_shared(As);
    const unsigned bsb = (unsigned)__cvta_generic_to_shared(Bs);

    float acc[4][4][4];
#pragma unroll
    for (int i = 0; i < 4; i++)
#pragma unroll
        for (int j = 0; j < 4; j++)
#pragma unroll
            for (int k = 0; k < 4; k++) acc[i][j][k] = 0.f;

    const int ar = tid >> 1, ac = (tid & 1) * 32;
    const int br = tid >> 2, bc = (tid & 3) * 32;
    const int arow = lane & 15;
    const int koff = (lane & 16) ? 8 : 0;
    const int trow = (lane & 7) + ((lane >> 3) & 3) * 8;

    for (int kb = 0; kb < CDIM; kb += 64) {
        // A tile: fp16 copy from g_Y
        {
            const __half* src = g_Y + (size_t)(m0 + ar) * CDIM + kb + ac;
            __half* dst = As + ar * ASTR + ac;
#pragma unroll
            for (int v = 0; v < 4; v++)
                *(uint4*)(dst + v * 8) = *(const uint4*)(src + v * 8);
        }
        // B tile: fp32 -> fp16
        {
            const float* src = W + (size_t)(kb + br) * CDIM + n0 + bc;
            __half* dst = Bs + br * BSTR + bc;
#pragma unroll
            for (int v = 0; v < 4; v++) *(uint4*)(dst + v * 8) = cvt8(src + v * 8);
        }
        __syncthreads();

#pragma unroll
        for (int kc = 0; kc < 2; kc++) {
            unsigned af[2][4][4], bb[4][4];
#pragma unroll
            for (int mf = 0; mf < 4; mf++) {
                const unsigned base = asb +
                    (unsigned)((m0w + mf * 16 + arow) * ASTR + kc * 32 + koff) * 2u;
                ldsm4(base,      af[0][mf][0], af[0][mf][1], af[0][mf][2], af[0][mf][3]);
                ldsm4(base + 32, af[1][mf][0], af[1][mf][1], af[1][mf][2], af[1][mf][3]);
            }
#pragma unroll
            for (int nf = 0; nf < 4; nf++) {
                ldsm4t(bsb + (unsigned)((kc * 32 + trow) * BSTR + n0w + nf * 8) * 2u,
                       bb[nf][0], bb[nf][1], bb[nf][2], bb[nf][3]);
            }
#pragma unroll
            for (int mf = 0; mf < 4; mf++)
#pragma unroll
                for (int nf = 0; nf < 4; nf++) {
                    mma16(acc[mf][nf], af[0][mf], bb[nf][0], bb[nf][1]);
                    mma16(acc[mf][nf], af[1][mf], bb[nf][2], bb[nf][3]);
                }
        }
        __syncthreads();
    }

#pragma unroll
    for (int mf = 0; mf < 4; mf++) {
        const int r0 = m0 + m0w + mf * 16 + g;
#pragma unroll
        for (int nf = 0; nf < 4; nf++) {
            const int c0 = n0 + n0w + nf * 8 + 2 * t;
            const float b0 = bias[c0], b1 = bias[c0 + 1];
            *(float2*)&out[(size_t)r0 * CDIM + c0] =
                make_float2(acc[mf][nf][0] + b0, acc[mf][nf][1] + b1);
            *(float2*)&out[(size_t)(r0 + 8) * CDIM + c0] =
                make_float2(acc[mf][nf][2] + b0, acc[mf][nf][3] + b1);
        }
    }
}

// ---------------------------------------------------------------------------
extern "C" void kernel_launch(void* const* d_in, const int* in_sizes, int n_in,
                              void* d_out, int out_size)
{
    const float* x     = (const float*)d_in[0];
    const float* Wqkv  = (const float*)d_in[1];
    const float* bqkv  = (const float*)d_in[2];
    const float* Wproj = (const float*)d_in[3];
    const float* bproj = (const float*)d_in[4];
    float* out = (float*)d_out;

    qkv_gemm_f16<<<dim3(NQKV / 128, MTOK / 128), 256>>>(x, Wqkv, bqkv);
    attn_fa16<<<dim3(TSEQ / 128, BH), 256>>>();
    proj_gemm_f16<<<dim3(CDIM / 128, MTOK / 128), 256>>>(Wproj, bproj, out);
}

// round 5
// speedup vs baseline: 6.8059x; 1.4459x over previous
#include <cuda_runtime.h>
#include <cuda_fp16.h>
#include <math.h>

#define BSZ 2
#define TSEQ 4096
#define CDIM 768
#define NH 12
#define HD 64
#define MTOK (BSZ * TSEQ)      // 8192
#define NQKV (3 * CDIM)        // 2304
#define BH (BSZ * NH)          // 24

// Scratch (allocation-free rule: device globals) — all fp16
__device__ __half g_Q[(size_t)BH * TSEQ * HD];   // [b*H+h, T, D], pre-scaled
__device__ __half g_K[(size_t)BH * TSEQ * HD];
__device__ __half g_V[(size_t)BH * TSEQ * HD];
__device__ __half g_Y[(size_t)MTOK * CDIM];      // attention out, [B*T, C]
__device__ __half g_Xh[(size_t)MTOK * CDIM];     // x in fp16
__device__ __half g_Wqkvh[(size_t)CDIM * NQKV];  // Wqkv in fp16
__device__ __half g_Wprojh[(size_t)CDIM * CDIM]; // Wproj in fp16

// ---------------------------------------------------------------------------
// helpers
// ---------------------------------------------------------------------------
__device__ __forceinline__ void mma16(float* c, const unsigned* a, unsigned b0, unsigned b1) {
    asm volatile(
        "mma.sync.aligned.m16n8k16.row.col.f32.f16.f16.f32 "
        "{%0,%1,%2,%3}, {%4,%5,%6,%7}, {%8,%9}, {%0,%1,%2,%3};"
        : "+f"(c[0]), "+f"(c[1]), "+f"(c[2]), "+f"(c[3])
        : "r"(a[0]), "r"(a[1]), "r"(a[2]), "r"(a[3]), "r"(b0), "r"(b1));
}
__device__ __forceinline__ void ldsm4(unsigned addr, unsigned& r0, unsigned& r1,
                                      unsigned& r2, unsigned& r3) {
    asm volatile("ldmatrix.sync.aligned.m8n8.x4.shared.b16 {%0,%1,%2,%3}, [%4];"
                 : "=r"(r0), "=r"(r1), "=r"(r2), "=r"(r3) : "r"(addr));
}
__device__ __forceinline__ void ldsm4t(unsigned addr, unsigned& r0, unsigned& r1,
                                       unsigned& r2, unsigned& r3) {
    asm volatile("ldmatrix.sync.aligned.m8n8.x4.trans.shared.b16 {%0,%1,%2,%3}, [%4];"
                 : "=r"(r0), "=r"(r1), "=r"(r2), "=r"(r3) : "r"(addr));
}
__device__ __forceinline__ float ex2(float x) {
    float r;
    asm("ex2.approx.f32 %0, %1;" : "=f"(r) : "f"(x));
    return r;
}
__device__ __forceinline__ unsigned packh2(float a, float b) {
    __half2 h = __floats2half2_rn(a, b);
    return *(unsigned*)&h;
}
__device__ __forceinline__ uint4 cvt8(const float* p) {
    float4 f0 = *(const float4*)p;
    float4 f1 = *(const float4*)(p + 4);
    uint4 u;
    u.x = packh2(f0.x, f0.y); u.y = packh2(f0.z, f0.w);
    u.z = packh2(f1.x, f1.y); u.w = packh2(f1.z, f1.w);
    return u;
}
__device__ __forceinline__ void cpa16(unsigned dst, const void* src) {
    asm volatile("cp.async.cg.shared.global [%0], [%1], 16;" :: "r"(dst), "l"(src));
}
#define CPCOMMIT() asm volatile("cp.async.commit_group;")
#define CPWAIT1()  asm volatile("cp.async.wait_group 1;")

#define QS (0.125f * 1.4426950408889634f)   // 1/sqrt(D) * log2(e)

// ---------------------------------------------------------------------------
// Kernel 0: fp32 -> fp16 convert (pre-pass)
// ---------------------------------------------------------------------------
__global__ __launch_bounds__(256) void f2h_kernel(const float* __restrict__ src,
                                                  __half* __restrict__ dst, int n)
{
    const int i = ((int)blockIdx.x * 256 + (int)threadIdx.x) * 8;
    if (i < n) *(uint4*)(dst + i) = cvt8(src + i);
}

// ---------------------------------------------------------------------------
// Kernel 1: QKV GEMM (fp16 mma + ldmatrix + 3-stage cp.async pipeline)
// g_Xh[8192,768] @ g_Wqkvh[768,2304] + bias -> scatter head-major Q/K/V fp16.
// 128x128x64 tile, 256 threads (8 warps, warp tile 64x32).
// ---------------------------------------------------------------------------
#define ASTR 72
#define BSTR 136
#define STAGEH (128 * ASTR + 64 * BSTR)   // halves per stage (17920)
#define NSTAGE 3
#define GEMM_SMEM (NSTAGE * STAGEH * 2)   // 107520 bytes

__device__ __forceinline__ void scatter_qkv2(int m, int n, float v0, float v1) {
    const int b = m >> 12;
    const int tt = m & 4095;
    const int sel = n / CDIM;            // 0=Q,1=K,2=V
    const int r = n - sel * CDIM;
    const int h = r >> 6;
    const int d = r & 63;
    if (sel == 0) { v0 *= QS; v1 *= QS; }
    __half* dst = (sel == 0) ? g_Q : ((sel == 1) ? g_K : g_V);
    *(__half2*)&dst[((size_t)(b * NH + h) * TSEQ + tt) * HD + d] = __floats2half2_rn(v0, v1);
}

template <bool IS_QKV>
__device__ __forceinline__ void gemm_f16_body(const __half* __restrict__ Ag,
                                              const __half* __restrict__ Bg,
                                              const float* __restrict__ bias,
                                              float* __restrict__ out, int ldb)
{
    extern __shared__ __half dsm[];
    const unsigned smb = (unsigned)__cvta_generic_to_shared(dsm);

    const int tid = (int)threadIdx.x;
    const int lane = tid & 31;
    const int wid = tid >> 5;
    const int g = lane >> 2;
    const int t = lane & 3;
    const int m0 = blockIdx.y * 128;
    const int n0 = blockIdx.x * 128;
    const int m0w = (wid & 1) * 64;
    const int n0w = (wid >> 1) * 32;

    float acc[4][4][4];
#pragma unroll
    for (int i = 0; i < 4; i++)
#pragma unroll
        for (int j = 0; j < 4; j++)
#pragma unroll
            for (int k = 0; k < 4; k++) acc[i][j][k] = 0.f;

    const int ar = tid >> 1, ac = (tid & 1) * 32;
    const int br = tid >> 2, bc = (tid & 3) * 32;
    const int arow = lane & 15;
    const int koff = (lane & 16) ? 8 : 0;
    const int trow = (lane & 7) + ((lane >> 3) & 3) * 8;

    const int NIT = CDIM / 64;   // 12

    // prefetch helper (stage s, k-block kb)
    auto prefetch = [&](int kb, int s) {
        const unsigned abase = smb + (unsigned)(s * STAGEH) * 2u;
        const unsigned bbase = abase + (unsigned)(128 * ASTR) * 2u;
        const __half* asrc = Ag + (size_t)(m0 + ar) * CDIM + kb + ac;
        const unsigned adst = abase + (unsigned)(ar * ASTR + ac) * 2u;
#pragma unroll
        for (int v = 0; v < 4; v++) cpa16(adst + v * 16u, asrc + v * 8);
        const __half* bsrc = Bg + (size_t)(kb + br) * ldb + n0 + bc;
        const unsigned bdst = bbase + (unsigned)(br * BSTR + bc) * 2u;
#pragma unroll
        for (int v = 0; v < 4; v++) cpa16(bdst + v * 16u, bsrc + v * 8);
    };

    prefetch(0, 0); CPCOMMIT();
    prefetch(64, 1); CPCOMMIT();

    for (int it = 0; it < NIT; it++) {
        CPWAIT1();
        __syncthreads();
        if (it + 2 < NIT) prefetch((it + 2) * 64, (it + 2) % NSTAGE);
        CPCOMMIT();

        const int s = it % NSTAGE;
        const unsigned asb = smb + (unsigned)(s * STAGEH) * 2u;
        const unsigned bsb = asb + (unsigned)(128 * ASTR) * 2u;

#pragma unroll
        for (int kc = 0; kc < 2; kc++) {
            unsigned af[2][4][4], bb[4][4];
#pragma unroll
            for (int mf = 0; mf < 4; mf++) {
                const unsigned base = asb +
                    (unsigned)((m0w + mf * 16 + arow) * ASTR + kc * 32 + koff) * 2u;
                ldsm4(base,      af[0][mf][0], af[0][mf][1], af[0][mf][2], af[0][mf][3]);
                ldsm4(base + 32, af[1][mf][0], af[1][mf][1], af[1][mf][2], af[1][mf][3]);
            }
#pragma unroll
            for (int nf = 0; nf < 4; nf++) {
                ldsm4t(bsb + (unsigned)((kc * 32 + trow) * BSTR + n0w + nf * 8) * 2u,
                       bb[nf][0], bb[nf][1], bb[nf][2], bb[nf][3]);
            }
#pragma unroll
            for (int mf = 0; mf < 4; mf++)
#pragma unroll
                for (int nf = 0; nf < 4; nf++) {
                    mma16(acc[mf][nf], af[0][mf], bb[nf][0], bb[nf][1]);
                    mma16(acc[mf][nf], af[1][mf], bb[nf][2], bb[nf][3]);
                }
        }
    }

#pragma unroll
    for (int mf = 0; mf < 4; mf++) {
        const int r0 = m0 + m0w + mf * 16 + g;
#pragma unroll
        for (int nf = 0; nf < 4; nf++) {
            const int c0 = n0 + n0w + nf * 8 + 2 * t;
            const float b0 = bias[c0], b1 = bias[c0 + 1];
            if (IS_QKV) {
                scatter_qkv2(r0,     c0, acc[mf][nf][0] + b0, acc[mf][nf][1] + b1);
                scatter_qkv2(r0 + 8, c0, acc[mf][nf][2] + b0, acc[mf][nf][3] + b1);
            } else {
                *(float2*)&out[(size_t)r0 * CDIM + c0] =
                    make_float2(acc[mf][nf][0] + b0, acc[mf][nf][1] + b1);
                *(float2*)&out[(size_t)(r0 + 8) * CDIM + c0] =
                    make_float2(acc[mf][nf][2] + b0, acc[mf][nf][3] + b1);
            }
        }
    }
}

__global__ __launch_bounds__(256) void qkv_gemm_f16(const float* __restrict__ bias)
{
    gemm_f16_body<true>(g_Xh, g_Wqkvh, bias, nullptr, NQKV);
}

__global__ __launch_bounds__(256) void proj_gemm_f16(const float* __restrict__ bias,
                                                     float* __restrict__ out)
{
    gemm_f16_body<false>(g_Y, g_Wprojh, bias, out, CDIM);
}

// ---------------------------------------------------------------------------
// Kernel 2: causal flash attention, fp16 mma, 2-stage cp.async K/V pipeline.
// Block = 128 q x 64 kv, 8 warps (warp = 16 q-rows x full kv width).
// ---------------------------------------------------------------------------
#define KVSTR 72
#define KVBUF (64 * KVSTR)      // halves per K or V buffer (4608)

__global__ __launch_bounds__(256) void attn_fa16()
{
    __shared__ __half sm[2 * 2 * KVBUF];   // [stage][K|V], 36864 B; Q staged in stage 0+1 K/V of stage0? (uses first 128*72 halves)
    const unsigned smb = (unsigned)__cvta_generic_to_shared(sm);

    const int qt  = (int)gridDim.x - 1 - (int)blockIdx.x;
    const int bh  = (int)blockIdx.y;
    const int tid = (int)threadIdx.x;
    const int lane = tid & 31;
    const int wid  = tid >> 5;
    const int g = lane >> 2;
    const int t = lane & 3;

    const __half* Qg = g_Q + (size_t)bh * TSEQ * HD + (size_t)qt * 128 * HD;
    const __half* Kg = g_K + (size_t)bh * TSEQ * HD;
    const __half* Vg = g_V + (size_t)bh * TSEQ * HD;

    // ---- stage Q via cp.async into sm[0 .. 128*72) (spans both stage-0 buffers)
    {
        const int r = tid >> 1;
        const int c0 = (tid & 1) * 32;
        const __half* src = Qg + r * 64 + c0;
        const unsigned dst = smb + (unsigned)(r * KVSTR + c0) * 2u;
#pragma unroll
        for (int v = 0; v < 4; v++) cpa16(dst + v * 16u, src + v * 8);
        CPCOMMIT();
        asm volatile("cp.async.wait_group 0;");
    }
    __syncthreads();

    unsigned qf[4][4];
    {
        const int qrow = wid * 16 + (lane & 15);
        const int koff = (lane & 16) ? 8 : 0;
#pragma unroll
        for (int ks = 0; ks < 4; ks++)
            ldsm4(smb + (unsigned)(qrow * KVSTR + ks * 16 + koff) * 2u,
                  qf[ks][0], qf[ks][1], qf[ks][2], qf[ks][3]);
    }
    __syncthreads();

    float of[8][4];
#pragma unroll
    for (int i = 0; i < 8; i++)
#pragma unroll
        for (int j = 0; j < 4; j++) of[i][j] = 0.f;
    float m0 = -1e30f, m1 = -1e30f, l0 = 0.f, l1 = 0.f;

    const int r0 = qt * 128 + wid * 16 + g;
    const int r1 = r0 + 8;
    const int ntiles = 2 * qt + 2;

    // K/V prefetch: row = tid>>2, col = (tid&3)*16, two 16B chunks each
    const int kvr = tid >> 2;
    const int kvc = (tid & 3) * 16;
    auto prefetch_kv = [&](int jt, int s) {
        const unsigned kdst = smb + (unsigned)(s * 2 * KVBUF + kvr * KVSTR + kvc) * 2u;
        const unsigned vdst = kdst + (unsigned)KVBUF * 2u;
        const __half* ks = Kg + (size_t)(jt * 64 + kvr) * 64 + kvc;
        const __half* vs = Vg + (size_t)(jt * 64 + kvr) * 64 + kvc;
        cpa16(kdst,       ks);
        cpa16(kdst + 16u, ks + 8);
        cpa16(vdst,       vs);
        cpa16(vdst + 16u, vs + 8);
    };

    prefetch_kv(0, 0); CPCOMMIT();

    for (int jt = 0; jt < ntiles; jt++) {
        if (jt + 1 < ntiles) prefetch_kv(jt + 1, (jt + 1) & 1);
        CPCOMMIT();
        CPWAIT1();
        __syncthreads();

        const int s = jt & 1;
        const unsigned kb = smb + (unsigned)(s * 2 * KVBUF) * 2u;
        const unsigned vb = kb + (unsigned)KVBUF * 2u;

        // ---- S = Q K^T
        float sa[8][4];
#pragma unroll
        for (int i = 0; i < 8; i++)
#pragma unroll
            for (int j = 0; j < 4; j++) sa[i][j] = 0.f;

        {
            const int nrow = (lane & 7);
            const int kc = ((lane >> 3) & 3) * 8;
#pragma unroll
            for (int nf = 0; nf < 8; nf++) {
                unsigned b0, b1, b2, b3;
                ldsm4(kb + (unsigned)((nf * 8 + nrow) * KVSTR + kc) * 2u, b0, b1, b2, b3);
                mma16(sa[nf], qf[0], b0, b1);
                mma16(sa[nf], qf[1], b2, b3);
                ldsm4(kb + (unsigned)((nf * 8 + nrow) * KVSTR + 32 + kc) * 2u, b0, b1, b2, b3);
                mma16(sa[nf], qf[2], b0, b1);
                mma16(sa[nf], qf[3], b2, b3);
            }
        }

        // ---- causal mask
        if (jt * 64 + 63 > qt * 128 + wid * 16) {
#pragma unroll
            for (int nf = 0; nf < 8; nf++) {
                const int c = jt * 64 + nf * 8 + 2 * t;
                if (c > r0)     sa[nf][0] = -1e30f;
                if (c + 1 > r0) sa[nf][1] = -1e30f;
                if (c > r1)     sa[nf][2] = -1e30f;
                if (c + 1 > r1) sa[nf][3] = -1e30f;
            }
        }

        // ---- online softmax
        float mx0 = -1e30f, mx1 = -1e30f;
#pragma unroll
        for (int nf = 0; nf < 8; nf++) {
            mx0 = fmaxf(mx0, fmaxf(sa[nf][0], sa[nf][1]));
            mx1 = fmaxf(mx1, fmaxf(sa[nf][2], sa[nf][3]));
        }
        mx0 = fmaxf(mx0, __shfl_xor_sync(0xffffffffu, mx0, 1));
        mx0 = fmaxf(mx0, __shfl_xor_sync(0xffffffffu, mx0, 2));
        mx1 = fmaxf(mx1, __shfl_xor_sync(0xffffffffu, mx1, 1));
        mx1 = fmaxf(mx1, __shfl_xor_sync(0xffffffffu, mx1, 2));

        const float nm0 = fmaxf(m0, mx0);
        const float nm1 = fmaxf(m1, mx1);
        const float cr0 = ex2(m0 - nm0);
        const float cr1 = ex2(m1 - nm1);
        m0 = nm0; m1 = nm1;

        float ls0 = 0.f, ls1 = 0.f;
#pragma unroll
        for (int nf = 0; nf < 8; nf++) {
            sa[nf][0] = ex2(sa[nf][0] - nm0);
            sa[nf][1] = ex2(sa[nf][1] - nm0);
            sa[nf][2] = ex2(sa[nf][2] - nm1);
            sa[nf][3] = ex2(sa[nf][3] - nm1);
            ls0 += sa[nf][0] + sa[nf][1];
            ls1 += sa[nf][2] + sa[nf][3];
        }
        ls0 += __shfl_xor_sync(0xffffffffu, ls0, 1);
        ls0 += __shfl_xor_sync(0xffffffffu, ls0, 2);
        ls1 += __shfl_xor_sync(0xffffffffu, ls1, 1);
        ls1 += __shfl_xor_sync(0xffffffffu, ls1, 2);
        l0 = l0 * cr0 + ls0;
        l1 = l1 * cr1 + ls1;

#pragma unroll
        for (int df = 0; df < 8; df++) {
            of[df][0] *= cr0; of[df][1] *= cr0;
            of[df][2] *= cr1; of[df][3] *= cr1;
        }

        // ---- P -> fp16 A-fragments
        unsigned pf[4][4];
#pragma unroll
        for (int kc = 0; kc < 4; kc++) {
            pf[kc][0] = packh2(sa[2 * kc][0],     sa[2 * kc][1]);
            pf[kc][1] = packh2(sa[2 * kc][2],     sa[2 * kc][3]);
            pf[kc][2] = packh2(sa[2 * kc + 1][0], sa[2 * kc + 1][1]);
            pf[kc][3] = packh2(sa[2 * kc + 1][2], sa[2 * kc + 1][3]);
        }

        // ---- O += P V
        {
            const int vrow = (lane & 7) + ((lane >> 3) & 3) * 8;
#pragma unroll
            for (int df = 0; df < 8; df++) {
                unsigned b0, b1, b2, b3;
                ldsm4t(vb + (unsigned)(vrow * KVSTR + df * 8) * 2u, b0, b1, b2, b3);
                mma16(of[df], pf[0], b0, b1);
                mma16(of[df], pf[1], b2, b3);
                ldsm4t(vb + (unsigned)((vrow + 32) * KVSTR + df * 8) * 2u, b0, b1, b2, b3);
                mma16(of[df], pf[2], b0, b1);
                mma16(of[df], pf[3], b2, b3);
            }
        }
        __syncthreads();
    }

    // ---- epilogue: normalize, write g_Y (fp16) in [B*T, C]
    const int b = bh / NH;
    const int h = bh % NH;
    const float il0 = 1.f / l0;
    const float il1 = 1.f / l1;
#pragma unroll
    for (int df = 0; df < 8; df++) {
        const int col = h * 64 + df * 8 + 2 * t;
        *(__half2*)&g_Y[(size_t)(b * TSEQ + r0) * CDIM + col] =
            __floats2half2_rn(of[df][0] * il0, of[df][1] * il0);
        *(__half2*)&g_Y[(size_t)(b * TSEQ + r1) * CDIM + col] =
            __floats2half2_rn(of[df][2] * il1, of[df][3] * il1);
    }
}

// ---------------------------------------------------------------------------
extern "C" void kernel_launch(void* const* d_in, const int* in_sizes, int n_in,
                              void* d_out, int out_size)
{
    const float* x     = (const float*)d_in[0];
    const float* Wqkv  = (const float*)d_in[1];
    const float* bqkv  = (const float*)d_in[2];
    const float* Wproj = (const float*)d_in[3];
    const float* bproj = (const float*)d_in[4];
    float* out = (float*)d_out;

    __half *xh, *wqh, *wph;
    cudaGetSymbolAddress((void**)&xh,  g_Xh);
    cudaGetSymbolAddress((void**)&wqh, g_Wqkvh);
    cudaGetSymbolAddress((void**)&wph, g_Wprojh);

    cudaFuncSetAttribute(qkv_gemm_f16, cudaFuncAttributeMaxDynamicSharedMemorySize, GEMM_SMEM);
    cudaFuncSetAttribute(proj_gemm_f16, cudaFuncAttributeMaxDynamicSharedMemorySize, GEMM_SMEM);

    f2h_kernel<<<(MTOK * CDIM) / 2048, 256>>>(x, xh, MTOK * CDIM);
    f2h_kernel<<<(CDIM * NQKV) / 2048, 256>>>(Wqkv, wqh, CDIM * NQKV);
    f2h_kernel<<<(CDIM * CDIM) / 2048, 256>>>(Wproj, wph, CDIM * CDIM);

    qkv_gemm_f16<<<dim3(NQKV / 128, MTOK / 128), 256, GEMM_SMEM>>>(bqkv);
    attn_fa16<<<dim3(TSEQ / 128, BH), 256>>>();
    proj_gemm_f16<<<dim3(CDIM / 128, MTOK / 128), 256, GEMM_SMEM>>>(bproj, out);
}

// round 6
// speedup vs baseline: 7.1208x; 1.0463x over previous
#include <cuda_runtime.h>
#include <cuda_fp16.h>
#include <math.h>

#define BSZ 2
#define TSEQ 4096
#define CDIM 768
#define NH 12
#define HD 64
#define MTOK (BSZ * TSEQ)      // 8192
#define NQKV (3 * CDIM)        // 2304
#define BH (BSZ * NH)          // 24

// Scratch (allocation-free rule: device globals) — all fp16
__device__ __half g_Q[(size_t)BH * TSEQ * HD];   // [b*H+h, T, D], pre-scaled
__device__ __half g_K[(size_t)BH * TSEQ * HD];
__device__ __half g_V[(size_t)BH * TSEQ * HD];
__device__ __half g_Y[(size_t)MTOK * CDIM];      // attention out, [B*T, C]
__device__ __half g_Xh[(size_t)MTOK * CDIM];     // x in fp16
__device__ __half g_Wqkvh[(size_t)CDIM * NQKV];  // Wqkv in fp16
__device__ __half g_Wprojh[(size_t)CDIM * CDIM]; // Wproj in fp16

// ---------------------------------------------------------------------------
// helpers
// ---------------------------------------------------------------------------
__device__ __forceinline__ void mma16(float* c, const unsigned* a, unsigned b0, unsigned b1) {
    asm volatile(
        "mma.sync.aligned.m16n8k16.row.col.f32.f16.f16.f32 "
        "{%0,%1,%2,%3}, {%4,%5,%6,%7}, {%8,%9}, {%0,%1,%2,%3};"
        : "+f"(c[0]), "+f"(c[1]), "+f"(c[2]), "+f"(c[3])
        : "r"(a[0]), "r"(a[1]), "r"(a[2]), "r"(a[3]), "r"(b0), "r"(b1));
}
__device__ __forceinline__ void ldsm4(unsigned addr, unsigned& r0, unsigned& r1,
                                      unsigned& r2, unsigned& r3) {
    asm volatile("ldmatrix.sync.aligned.m8n8.x4.shared.b16 {%0,%1,%2,%3}, [%4];"
                 : "=r"(r0), "=r"(r1), "=r"(r2), "=r"(r3) : "r"(addr));
}
__device__ __forceinline__ void ldsm4t(unsigned addr, unsigned& r0, unsigned& r1,
                                       unsigned& r2, unsigned& r3) {
    asm volatile("ldmatrix.sync.aligned.m8n8.x4.trans.shared.b16 {%0,%1,%2,%3}, [%4];"
                 : "=r"(r0), "=r"(r1), "=r"(r2), "=r"(r3) : "r"(addr));
}
__device__ __forceinline__ float ex2(float x) {
    float r;
    asm("ex2.approx.f32 %0, %1;" : "=f"(r) : "f"(x));
    return r;
}
__device__ __forceinline__ unsigned packh2(float a, float b) {
    __half2 h = __floats2half2_rn(a, b);
    return *(unsigned*)&h;
}
__device__ __forceinline__ uint4 cvt8(const float* p) {
    float4 f0 = *(const float4*)p;
    float4 f1 = *(const float4*)(p + 4);
    uint4 u;
    u.x = packh2(f0.x, f0.y); u.y = packh2(f0.z, f0.w);
    u.z = packh2(f1.x, f1.y); u.w = packh2(f1.z, f1.w);
    return u;
}
__device__ __forceinline__ void cpa16(unsigned dst, const void* src) {
    asm volatile("cp.async.cg.shared.global [%0], [%1], 16;" :: "r"(dst), "l"(src));
}
#define CPCOMMIT() asm volatile("cp.async.commit_group;")
#define CPWAIT1()  asm volatile("cp.async.wait_group 1;")

#define QS (0.125f * 1.4426950408889634f)   // 1/sqrt(D) * log2(e)

// ---------------------------------------------------------------------------
// Kernel 0: fp32 -> fp16 convert (pre-pass)
// ---------------------------------------------------------------------------
__global__ __launch_bounds__(256) void f2h_kernel(const float* __restrict__ src,
                                                  __half* __restrict__ dst, int n)
{
    const int i = ((int)blockIdx.x * 256 + (int)threadIdx.x) * 8;
    if (i < n) *(uint4*)(dst + i) = cvt8(src + i);
}

// ---------------------------------------------------------------------------
// GEMM (fp16 mma + ldmatrix + 2-stage cp.async, 2 CTAs/SM)
// 128x128x64 tile, 256 threads (8 warps, warp tile 64x32).
// ---------------------------------------------------------------------------
#define ASTR 72
#define BSTR 136
#define STAGEH (128 * ASTR + 64 * BSTR)   // halves per stage (17920)
#define NSTAGE 2
#define GEMM_SMEM (NSTAGE * STAGEH * 2)   // 71680 bytes

__device__ __forceinline__ void scatter_qkv2(int m, int n, float v0, float v1) {
    const int b = m >> 12;
    const int tt = m & 4095;
    const int sel = n / CDIM;            // 0=Q,1=K,2=V
    const int r = n - sel * CDIM;
    const int h = r >> 6;
    const int d = r & 63;
    if (sel == 0) { v0 *= QS; v1 *= QS; }
    __half* dst = (sel == 0) ? g_Q : ((sel == 1) ? g_K : g_V);
    *(__half2*)&dst[((size_t)(b * NH + h) * TSEQ + tt) * HD + d] = __floats2half2_rn(v0, v1);
}

template <bool IS_QKV>
__device__ __forceinline__ void gemm_f16_body(const __half* __restrict__ Ag,
                                              const __half* __restrict__ Bg,
                                              const float* __restrict__ bias,
                                              float* __restrict__ out, int ldb)
{
    extern __shared__ __half dsm[];
    const unsigned smb = (unsigned)__cvta_generic_to_shared(dsm);

    const int tid = (int)threadIdx.x;
    const int lane = tid & 31;
    const int wid = tid >> 5;
    const int g = lane >> 2;
    const int t = lane & 3;
    const int m0 = blockIdx.y * 128;
    const int n0 = blockIdx.x * 128;
    const int m0w = (wid & 1) * 64;
    const int n0w = (wid >> 1) * 32;

    float acc[4][4][4];
#pragma unroll
    for (int i = 0; i < 4; i++)
#pragma unroll
        for (int j = 0; j < 4; j++)
#pragma unroll
            for (int k = 0; k < 4; k++) acc[i][j][k] = 0.f;

    const int ar = tid >> 1, ac = (tid & 1) * 32;
    const int br = tid >> 2, bc = (tid & 3) * 32;
    const int arow = lane & 15;
    const int koff = (lane & 16) ? 8 : 0;
    const int trow = (lane & 7) + ((lane >> 3) & 3) * 8;

    const int NIT = CDIM / 64;   // 12

    auto prefetch = [&](int kb, int s) {
        const unsigned abase = smb + (unsigned)(s * STAGEH) * 2u;
        const unsigned bbase = abase + (unsigned)(128 * ASTR) * 2u;
        const __half* asrc = Ag + (size_t)(m0 + ar) * CDIM + kb + ac;
        const unsigned adst = abase + (unsigned)(ar * ASTR + ac) * 2u;
#pragma unroll
        for (int v = 0; v < 4; v++) cpa16(adst + v * 16u, asrc + v * 8);
        const __half* bsrc = Bg + (size_t)(kb + br) * ldb + n0 + bc;
        const unsigned bdst = bbase + (unsigned)(br * BSTR + bc) * 2u;
#pragma unroll
        for (int v = 0; v < 4; v++) cpa16(bdst + v * 16u, bsrc + v * 8);
    };

    prefetch(0, 0); CPCOMMIT();

    for (int it = 0; it < NIT; it++) {
        if (it + 1 < NIT) prefetch((it + 1) * 64, (it + 1) & 1);
        CPCOMMIT();
        CPWAIT1();
        __syncthreads();

        const int s = it & 1;
        const unsigned asb = smb + (unsigned)(s * STAGEH) * 2u;
        const unsigned bsb = asb + (unsigned)(128 * ASTR) * 2u;

#pragma unroll
        for (int kc = 0; kc < 2; kc++) {
            unsigned bb[4][4];
#pragma unroll
            for (int nf = 0; nf < 4; nf++)
                ldsm4t(bsb + (unsigned)((kc * 32 + trow) * BSTR + n0w + nf * 8) * 2u,
                       bb[nf][0], bb[nf][1], bb[nf][2], bb[nf][3]);
#pragma unroll
            for (int mf = 0; mf < 4; mf++) {
                unsigned a0[4], a1[4];
                const unsigned base = asb +
                    (unsigned)((m0w + mf * 16 + arow) * ASTR + kc * 32 + koff) * 2u;
                ldsm4(base,      a0[0], a0[1], a0[2], a0[3]);
                ldsm4(base + 32, a1[0], a1[1], a1[2], a1[3]);
#pragma unroll
                for (int nf = 0; nf < 4; nf++) {
                    mma16(acc[mf][nf], a0, bb[nf][0], bb[nf][1]);
                    mma16(acc[mf][nf], a1, bb[nf][2], bb[nf][3]);
                }
            }
        }
        __syncthreads();
    }

#pragma unroll
    for (int mf = 0; mf < 4; mf++) {
        const int r0 = m0 + m0w + mf * 16 + g;
#pragma unroll
        for (int nf = 0; nf < 4; nf++) {
            const int c0 = n0 + n0w + nf * 8 + 2 * t;
            const float b0 = bias[c0], b1 = bias[c0 + 1];
            if (IS_QKV) {
                scatter_qkv2(r0,     c0, acc[mf][nf][0] + b0, acc[mf][nf][1] + b1);
                scatter_qkv2(r0 + 8, c0, acc[mf][nf][2] + b0, acc[mf][nf][3] + b1);
            } else {
                *(float2*)&out[(size_t)r0 * CDIM + c0] =
                    make_float2(acc[mf][nf][0] + b0, acc[mf][nf][1] + b1);
                *(float2*)&out[(size_t)(r0 + 8) * CDIM + c0] =
                    make_float2(acc[mf][nf][2] + b0, acc[mf][nf][3] + b1);
            }
        }
    }
}

__global__ __launch_bounds__(256, 2) void qkv_gemm_f16(const float* __restrict__ bias)
{
    gemm_f16_body<true>(g_Xh, g_Wqkvh, bias, nullptr, NQKV);
}

__global__ __launch_bounds__(256, 2) void proj_gemm_f16(const float* __restrict__ bias,
                                                        float* __restrict__ out)
{
    gemm_f16_body<false>(g_Y, g_Wprojh, bias, out, CDIM);
}

// ---------------------------------------------------------------------------
// Kernel 2: causal flash attention (unchanged from R5)
// ---------------------------------------------------------------------------
#define KVSTR 72
#define KVBUF (64 * KVSTR)

__global__ __launch_bounds__(256) void attn_fa16()
{
    __shared__ __half sm[2 * 2 * KVBUF];
    const unsigned smb = (unsigned)__cvta_generic_to_shared(sm);

    const int qt  = (int)gridDim.x - 1 - (int)blockIdx.x;
    const int bh  = (int)blockIdx.y;
    const int tid = (int)threadIdx.x;
    const int lane = tid & 31;
    const int wid  = tid >> 5;
    const int g = lane >> 2;
    const int t = lane & 3;

    const __half* Qg = g_Q + (size_t)bh * TSEQ * HD + (size_t)qt * 128 * HD;
    const __half* Kg = g_K + (size_t)bh * TSEQ * HD;
    const __half* Vg = g_V + (size_t)bh * TSEQ * HD;

    {
        const int r = tid >> 1;
        const int c0 = (tid & 1) * 32;
        const __half* src = Qg + r * 64 + c0;
        const unsigned dst = smb + (unsigned)(r * KVSTR + c0) * 2u;
#pragma unroll
        for (int v = 0; v < 4; v++) cpa16(dst + v * 16u, src + v * 8);
        CPCOMMIT();
        asm volatile("cp.async.wait_group 0;");
    }
    __syncthreads();

    unsigned qf[4][4];
    {
        const int qrow = wid * 16 + (lane & 15);
        const int koff = (lane & 16) ? 8 : 0;
#pragma unroll
        for (int ks = 0; ks < 4; ks++)
            ldsm4(smb + (unsigned)(qrow * KVSTR + ks * 16 + koff) * 2u,
                  qf[ks][0], qf[ks][1], qf[ks][2], qf[ks][3]);
    }
    __syncthreads();

    float of[8][4];
#pragma unroll
    for (int i = 0; i < 8; i++)
#pragma unroll
        for (int j = 0; j < 4; j++) of[i][j] = 0.f;
    float m0 = -1e30f, m1 = -1e30f, l0 = 0.f, l1 = 0.f;

    const int r0 = qt * 128 + wid * 16 + g;
    const int r1 = r0 + 8;
    const int ntiles = 2 * qt + 2;

    const int kvr = tid >> 2;
    const int kvc = (tid & 3) * 16;
    auto prefetch_kv = [&](int jt, int s) {
        const unsigned kdst = smb + (unsigned)(s * 2 * KVBUF + kvr * KVSTR + kvc) * 2u;
        const unsigned vdst = kdst + (unsigned)KVBUF * 2u;
        const __half* ks = Kg + (size_t)(jt * 64 + kvr) * 64 + kvc;
        const __half* vs = Vg + (size_t)(jt * 64 + kvr) * 64 + kvc;
        cpa16(kdst,       ks);
        cpa16(kdst + 16u, ks + 8);
        cpa16(vdst,       vs);
        cpa16(vdst + 16u, vs + 8);
    };

    prefetch_kv(0, 0); CPCOMMIT();

    for (int jt = 0; jt < ntiles; jt++) {
        if (jt + 1 < ntiles) prefetch_kv(jt + 1, (jt + 1) & 1);
        CPCOMMIT();
        CPWAIT1();
        __syncthreads();

        const int s = jt & 1;
        const unsigned kb = smb + (unsigned)(s * 2 * KVBUF) * 2u;
        const unsigned vb = kb + (unsigned)KVBUF * 2u;

        float sa[8][4];
#pragma unroll
        for (int i = 0; i < 8; i++)
#pragma unroll
            for (int j = 0; j < 4; j++) sa[i][j] = 0.f;

        {
            const int nrow = (lane & 7);
            const int kc = ((lane >> 3) & 3) * 8;
#pragma unroll
            for (int nf = 0; nf < 8; nf++) {
                unsigned b0, b1, b2, b3;
                ldsm4(kb + (unsigned)((nf * 8 + nrow) * KVSTR + kc) * 2u, b0, b1, b2, b3);
                mma16(sa[nf], qf[0], b0, b1);
                mma16(sa[nf], qf[1], b2, b3);
                ldsm4(kb + (unsigned)((nf * 8 + nrow) * KVSTR + 32 + kc) * 2u, b0, b1, b2, b3);
                mma16(sa[nf], qf[2], b0, b1);
                mma16(sa[nf], qf[3], b2, b3);
            }
        }

        if (jt * 64 + 63 > qt * 128 + wid * 16) {
#pragma unroll
            for (int nf = 0; nf < 8; nf++) {
                const int c = jt * 64 + nf * 8 + 2 * t;
                if (c > r0)     sa[nf][0] = -1e30f;
                if (c + 1 > r0) sa[nf][1] = -1e30f;
                if (c > r1)     sa[nf][2] = -1e30f;
                if (c + 1 > r1) sa[nf][3] = -1e30f;
            }
        }

        float mx0 = -1e30f, mx1 = -1e30f;
#pragma unroll
        for (int nf = 0; nf < 8; nf++) {
            mx0 = fmaxf(mx0, fmaxf(sa[nf][0], sa[nf][1]));
            mx1 = fmaxf(mx1, fmaxf(sa[nf][2], sa[nf][3]));
        }
        mx0 = fmaxf(mx0, __shfl_xor_sync(0xffffffffu, mx0, 1));
        mx0 = fmaxf(mx0, __shfl_xor_sync(0xffffffffu, mx0, 2));
        mx1 = fmaxf(mx1, __shfl_xor_sync(0xffffffffu, mx1, 1));
        mx1 = fmaxf(mx1, __shfl_xor_sync(0xffffffffu, mx1, 2));

        const float nm0 = fmaxf(m0, mx0);
        const float nm1 = fmaxf(m1, mx1);
        const float cr0 = ex2(m0 - nm0);
        const float cr1 = ex2(m1 - nm1);
        m0 = nm0; m1 = nm1;

        float ls0 = 0.f, ls1 = 0.f;
#pragma unroll
        for (int nf = 0; nf < 8; nf++) {
            sa[nf][0] = ex2(sa[nf][0] - nm0);
            sa[nf][1] = ex2(sa[nf][1] - nm0);
            sa[nf][2] = ex2(sa[nf][2] - nm1);
            sa[nf][3] = ex2(sa[nf][3] - nm1);
            ls0 += sa[nf][0] + sa[nf][1];
            ls1 += sa[nf][2] + sa[nf][3];
        }
        ls0 += __shfl_xor_sync(0xffffffffu, ls0, 1);
        ls0 += __shfl_xor_sync(0xffffffffu, ls0, 2);
        ls1 += __shfl_xor_sync(0xffffffffu, ls1, 1);
        ls1 += __shfl_xor_sync(0xffffffffu, ls1, 2);
        l0 = l0 * cr0 + ls0;
        l1 = l1 * cr1 + ls1;

#pragma unroll
        for (int df = 0; df < 8; df++) {
            of[df][0] *= cr0; of[df][1] *= cr0;
            of[df][2] *= cr1; of[df][3] *= cr1;
        }

        unsigned pf[4][4];
#pragma unroll
        for (int kc = 0; kc < 4; kc++) {
            pf[kc][0] = packh2(sa[2 * kc][0],     sa[2 * kc][1]);
            pf[kc][1] = packh2(sa[2 * kc][2],     sa[2 * kc][3]);
            pf[kc][2] = packh2(sa[2 * kc + 1][0], sa[2 * kc + 1][1]);
            pf[kc][3] = packh2(sa[2 * kc + 1][2], sa[2 * kc + 1][3]);
        }

        {
            const int vrow = (lane & 7) + ((lane >> 3) & 3) * 8;
#pragma unroll
            for (int df = 0; df < 8; df++) {
                unsigned b0, b1, b2, b3;
                ldsm4t(vb + (unsigned)(vrow * KVSTR + df * 8) * 2u, b0, b1, b2, b3);
                mma16(of[df], pf[0], b0, b1);
                mma16(of[df], pf[1], b2, b3);
                ldsm4t(vb + (unsigned)((vrow + 32) * KVSTR + df * 8) * 2u, b0, b1, b2, b3);
                mma16(of[df], pf[2], b0, b1);
                mma16(of[df], pf[3], b2, b3);
            }
        }
        __syncthreads();
    }

    const int b = bh / NH;
    const int h = bh % NH;
    const float il0 = 1.f / l0;
    const float il1 = 1.f / l1;
#pragma unroll
    for (int df = 0; df < 8; df++) {
        const int col = h * 64 + df * 8 + 2 * t;
        *(__half2*)&g_Y[(size_t)(b * TSEQ + r0) * CDIM + col] =
            __floats2half2_rn(of[df][0] * il0, of[df][1] * il0);
        *(__half2*)&g_Y[(size_t)(b * TSEQ + r1) * CDIM + col] =
            __floats2half2_rn(of[df][2] * il1, of[df][3] * il1);
    }
}

// ---------------------------------------------------------------------------
extern "C" void kernel_launch(void* const* d_in, const int* in_sizes, int n_in,
                              void* d_out, int out_size)
{
    const float* x     = (const float*)d_in[0];
    const float* Wqkv  = (const float*)d_in[1];
    const float* bqkv  = (const float*)d_in[2];
    const float* Wproj = (const float*)d_in[3];
    const float* bproj = (const float*)d_in[4];
    float* out = (float*)d_out;

    __half *xh, *wqh, *wph;
    cudaGetSymbolAddress((void**)&xh,  g_Xh);
    cudaGetSymbolAddress((void**)&wqh, g_Wqkvh);
    cudaGetSymbolAddress((void**)&wph, g_Wprojh);

    cudaFuncSetAttribute(qkv_gemm_f16, cudaFuncAttributeMaxDynamicSharedMemorySize, GEMM_SMEM);
    cudaFuncSetAttribute(proj_gemm_f16, cudaFuncAttributeMaxDynamicSharedMemorySize, GEMM_SMEM);

    f2h_kernel<<<(MTOK * CDIM) / 2048, 256>>>(x, xh, MTOK * CDIM);
    f2h_kernel<<<(CDIM * NQKV) / 2048, 256>>>(Wqkv, wqh, CDIM * NQKV);
    f2h_kernel<<<(CDIM * CDIM) / 2048, 256>>>(Wproj, wph, CDIM * CDIM);

    qkv_gemm_f16<<<dim3(NQKV / 128, MTOK / 128), 256, GEMM_SMEM>>>(bqkv);
    attn_fa16<<<dim3(TSEQ / 128, BH), 256>>>();
    proj_gemm_f16<<<dim3(CDIM / 128, MTOK / 128), 256, GEMM_SMEM>>>(bproj, out);
}

// round 9
// speedup vs baseline: 7.3120x; 1.0268x over previous
#include <cuda_runtime.h>
#include <cuda_fp16.h>
#include <math.h>

#define BSZ 2
#define TSEQ 4096
#define CDIM 768
#define NH 12
#define HD 64
#define MTOK (BSZ * TSEQ)      // 8192
#define NQKV (3 * CDIM)        // 2304
#define BH (BSZ * NH)          // 24

// Scratch (allocation-free rule: device globals) — all fp16
__device__ __half g_Q[(size_t)BH * TSEQ * HD];   // [b*H+h, T, D], pre-scaled
__device__ __half g_K[(size_t)BH * TSEQ * HD];
__device__ __half g_V[(size_t)BH * TSEQ * HD];
__device__ __half g_Y[(size_t)MTOK * CDIM];      // attention out, [B*T, C]
__device__ __half g_Xh[(size_t)MTOK * CDIM];     // x in fp16
__device__ __half g_Wqkvh[(size_t)CDIM * NQKV];  // Wqkv in fp16
__device__ __half g_Wprojh[(size_t)CDIM * CDIM]; // Wproj in fp16

// ---------------------------------------------------------------------------
// helpers
// ---------------------------------------------------------------------------
__device__ __forceinline__ void mma16(float* c, const unsigned* a, unsigned b0, unsigned b1) {
    asm volatile(
        "mma.sync.aligned.m16n8k16.row.col.f32.f16.f16.f32 "
        "{%0,%1,%2,%3}, {%4,%5,%6,%7}, {%8,%9}, {%0,%1,%2,%3};"
        : "+f"(c[0]), "+f"(c[1]), "+f"(c[2]), "+f"(c[3])
        : "r"(a[0]), "r"(a[1]), "r"(a[2]), "r"(a[3]), "r"(b0), "r"(b1));
}
__device__ __forceinline__ void ldsm4(unsigned addr, unsigned& r0, unsigned& r1,
                                      unsigned& r2, unsigned& r3) {
    asm volatile("ldmatrix.sync.aligned.m8n8.x4.shared.b16 {%0,%1,%2,%3}, [%4];"
                 : "=r"(r0), "=r"(r1), "=r"(r2), "=r"(r3) : "r"(addr));
}
__device__ __forceinline__ void ldsm4t(unsigned addr, unsigned& r0, unsigned& r1,
                                       unsigned& r2, unsigned& r3) {
    asm volatile("ldmatrix.sync.aligned.m8n8.x4.trans.shared.b16 {%0,%1,%2,%3}, [%4];"
                 : "=r"(r0), "=r"(r1), "=r"(r2), "=r"(r3) : "r"(addr));
}
__device__ __forceinline__ float ex2(float x) {
    float r;
    asm("ex2.approx.f32 %0, %1;" : "=f"(r) : "f"(x));
    return r;
}
__device__ __forceinline__ unsigned packh2(float a, float b) {
    __half2 h = __floats2half2_rn(a, b);
    return *(unsigned*)&h;
}
__device__ __forceinline__ uint4 cvt8(const float* p) {
    float4 f0 = *(const float4*)p;
    float4 f1 = *(const float4*)(p + 4);
    uint4 u;
    u.x = packh2(f0.x, f0.y); u.y = packh2(f0.z, f0.w);
    u.z = packh2(f1.x, f1.y); u.w = packh2(f1.z, f1.w);
    return u;
}
__device__ __forceinline__ void cpa16(unsigned dst, const void* src) {
    asm volatile("cp.async.cg.shared.global [%0], [%1], 16;" :: "r"(dst), "l"(src));
}
#define CPCOMMIT() asm volatile("cp.async.commit_group;")
#define CPWAIT0()  asm volatile("cp.async.wait_group 0;")
#define CPWAIT1()  asm volatile("cp.async.wait_group 1;")
#define CPWAIT2()  asm volatile("cp.async.wait_group 2;")

#define QS (0.125f * 1.4426950408889634f)   // 1/sqrt(D) * log2(e)

// ---------------------------------------------------------------------------
// Kernel 0: fp32 -> fp16 convert (pre-pass)
// ---------------------------------------------------------------------------
__global__ __launch_bounds__(256) void f2h_kernel(const float* __restrict__ src,
                                                  __half* __restrict__ dst, int n)
{
    const int i = ((int)blockIdx.x * 256 + (int)threadIdx.x) * 8;
    if (i < n) *(uint4*)(dst + i) = cvt8(src + i);
}

// ---------------------------------------------------------------------------
// GEMM (fp16 mma + ldmatrix + 3-stage cp.async, single sync/iter, 2 CTAs/SM)
// 128x128x64 tile, 256 threads (8 warps, warp tile 64x32).
// ---------------------------------------------------------------------------
#define ASTR 72
#define BSTR 136
#define STAGEH (128 * ASTR + 64 * BSTR)   // halves per stage (17920)
#define NSTAGE 3
#define GEMM_SMEM (NSTAGE * STAGEH * 2)   // 107520 bytes

__device__ __forceinline__ void scatter_qkv2(int m, int n, float v0, float v1) {
    const int b = m >> 12;
    const int tt = m & 4095;
    const int sel = n / CDIM;            // 0=Q,1=K,2=V
    const int r = n - sel * CDIM;
    const int h = r >> 6;
    const int d = r & 63;
    if (sel == 0) { v0 *= QS; v1 *= QS; }
    __half* dst = (sel == 0) ? g_Q : ((sel == 1) ? g_K : g_V);
    *(__half2*)&dst[((size_t)(b * NH + h) * TSEQ + tt) * HD + d] = __floats2half2_rn(v0, v1);
}

template <bool IS_QKV>
__device__ __forceinline__ void gemm_f16_body(const __half* __restrict__ Ag,
                                              const __half* __restrict__ Bg,
                                              const float* __restrict__ bias,
                                              float* __restrict__ out, int ldb)
{
    extern __shared__ __half dsm[];
    const unsigned smb = (unsigned)__cvta_generic_to_shared(dsm);

    const int tid = (int)threadIdx.x;
    const int lane = tid & 31;
    const int wid = tid >> 5;
    const int g = lane >> 2;
    const int t = lane & 3;
    const int m0 = blockIdx.y * 128;
    const int n0 = blockIdx.x * 128;
    const int m0w = (wid & 1) * 64;
    const int n0w = (wid >> 1) * 32;

    float acc[4][4][4];
#pragma unroll
    for (int i = 0; i < 4; i++)
#pragma unroll
        for (int j = 0; j < 4; j++)
#pragma unroll
            for (int k = 0; k < 4; k++) acc[i][j][k] = 0.f;

    const int ar = tid >> 1, ac = (tid & 1) * 32;
    const int br = tid >> 2, bc = (tid & 3) * 32;
    const int arow = lane & 15;
    const int koff = (lane & 16) ? 8 : 0;
    const int trow = (lane & 7) + ((lane >> 3) & 3) * 8;

    const int NIT = CDIM / 64;   // 12

    auto prefetch = [&](int it, int s) {
        const int kb = it * 64;
        const unsigned abase = smb + (unsigned)(s * STAGEH) * 2u;
        const unsigned bbase = abase + (unsigned)(128 * ASTR) * 2u;
        const __half* asrc = Ag + (size_t)(m0 + ar) * CDIM + kb + ac;
        const unsigned adst = abase + (unsigned)(ar * ASTR + ac) * 2u;
#pragma unroll
        for (int v = 0; v < 4; v++) cpa16(adst + v * 16u, asrc + v * 8);
        const __half* bsrc = Bg + (size_t)(kb + br) * ldb + n0 + bc;
        const unsigned bdst = bbase + (unsigned)(br * BSTR + bc) * 2u;
#pragma unroll
        for (int v = 0; v < 4; v++) cpa16(bdst + v * 16u, bsrc + v * 8);
    };

    prefetch(0, 0); CPCOMMIT();
    prefetch(1, 1); CPCOMMIT();

    int s = 0;         // stage of current iteration
    int ps = 2;        // stage of (it+2)
    for (int it = 0; it < NIT; it++) {
        CPWAIT1();
        __syncthreads();
        if (it + 2 < NIT) prefetch(it + 2, ps);
        CPCOMMIT();

        const unsigned asb = smb + (unsigned)(s * STAGEH) * 2u;
        const unsigned bsb = asb + (unsigned)(128 * ASTR) * 2u;

#pragma unroll
        for (int kc = 0; kc < 2; kc++) {
            unsigned bb[4][4];
#pragma unroll
            for (int nf = 0; nf < 4; nf++)
                ldsm4t(bsb + (unsigned)((kc * 32 + trow) * BSTR + n0w + nf * 8) * 2u,
                       bb[nf][0], bb[nf][1], bb[nf][2], bb[nf][3]);
#pragma unroll
            for (int mf = 0; mf < 4; mf++) {
                unsigned a0[4], a1[4];
                const unsigned base = asb +
                    (unsigned)((m0w + mf * 16 + arow) * ASTR + kc * 32 + koff) * 2u;
                ldsm4(base,      a0[0], a0[1], a0[2], a0[3]);
                ldsm4(base + 32, a1[0], a1[1], a1[2], a1[3]);
#pragma unroll
                for (int nf = 0; nf < 4; nf++) {
                    mma16(acc[mf][nf], a0, bb[nf][0], bb[nf][1]);
                    mma16(acc[mf][nf], a1, bb[nf][2], bb[nf][3]);
                }
            }
        }
        s = (s == 2) ? 0 : s + 1;
        ps = (ps == 2) ? 0 : ps + 1;
    }

#pragma unroll
    for (int mf = 0; mf < 4; mf++) {
        const int r0 = m0 + m0w + mf * 16 + g;
#pragma unroll
        for (int nf = 0; nf < 4; nf++) {
            const int c0 = n0 + n0w + nf * 8 + 2 * t;
            const float b0 = bias[c0], b1 = bias[c0 + 1];
            if (IS_QKV) {
                scatter_qkv2(r0,     c0, acc[mf][nf][0] + b0, acc[mf][nf][1] + b1);
                scatter_qkv2(r0 + 8, c0, acc[mf][nf][2] + b0, acc[mf][nf][3] + b1);
            } else {
                *(float2*)&out[(size_t)r0 * CDIM + c0] =
                    make_float2(acc[mf][nf][0] + b0, acc[mf][nf][1] + b1);
                *(float2*)&out[(size_t)(r0 + 8) * CDIM + c0] =
                    make_float2(acc[mf][nf][2] + b0, acc[mf][nf][3] + b1);
            }
        }
    }
}

__global__ __launch_bounds__(256, 2) void qkv_gemm_f16(const float* __restrict__ bias)
{
    gemm_f16_body<true>(g_Xh, g_Wqkvh, bias, nullptr, NQKV);
}

__global__ __launch_bounds__(256, 2) void proj_gemm_f16(const float* __restrict__ bias,
                                                        float* __restrict__ out)
{
    gemm_f16_body<false>(g_Y, g_Wprojh, bias, out, CDIM);
}

// ---------------------------------------------------------------------------
// Kernel 2: causal flash attention, fp16 mma, 4-stage cp.async K/V ring,
// single sync per tile. Block = 128 q x 64 kv, 8 warps.
// ---------------------------------------------------------------------------
#define KVSTR 72
#define KVBUF (64 * KVSTR)             // halves per K or V buffer (4608)
#define KVSTAGE 4
#define ATT_SMEM (KVSTAGE * 2 * KVBUF * 2)   // 73728 bytes

__global__ __launch_bounds__(256, 2) void attn_fa16()
{
    extern __shared__ __half sm[];
    const unsigned smb = (unsigned)__cvta_generic_to_shared(sm);

    const int qt  = (int)gridDim.x - 1 - (int)blockIdx.x;
    const int bh  = (int)blockIdx.y;
    const int tid = (int)threadIdx.x;
    const int lane = tid & 31;
    const int wid  = tid >> 5;
    const int g = lane >> 2;
    const int t = lane & 3;

    const __half* Qg = g_Q + (size_t)bh * TSEQ * HD + (size_t)qt * 128 * HD;
    const __half* Kg = g_K + (size_t)bh * TSEQ * HD;
    const __half* Vg = g_V + (size_t)bh * TSEQ * HD;

    // ---- stage Q into stage-0 region (consumed before ring starts)
    {
        const int r = tid >> 1;
        const int c0 = (tid & 1) * 32;
        const __half* src = Qg + r * 64 + c0;
        const unsigned dst = smb + (unsigned)(r * KVSTR + c0) * 2u;
#pragma unroll
        for (int v = 0; v < 4; v++) cpa16(dst + v * 16u, src + v * 8);
        CPCOMMIT();
        CPWAIT0();
    }
    __syncthreads();

    unsigned qf[4][4];
    {
        const int qrow = wid * 16 + (lane & 15);
        const int koff = (lane & 16) ? 8 : 0;
#pragma unroll
        for (int ks = 0; ks < 4; ks++)
            ldsm4(smb + (unsigned)(qrow * KVSTR + ks * 16 + koff) * 2u,
                  qf[ks][0], qf[ks][1], qf[ks][2], qf[ks][3]);
    }
    __syncthreads();

    float of[8][4];
#pragma unroll
    for (int i = 0; i < 8; i++)
#pragma unroll
        for (int j = 0; j < 4; j++) of[i][j] = 0.f;
    float m0 = -1e30f, m1 = -1e30f, l0 = 0.f, l1 = 0.f;

    const int r0 = qt * 128 + wid * 16 + g;
    const int r1 = r0 + 8;
    const int ntiles = 2 * qt + 2;

    const int kvr = tid >> 2;
    const int kvc = (tid & 3) * 16;
    auto prefetch_kv = [&](int jt, int s) {
        const unsigned kdst = smb + (unsigned)(s * 2 * KVBUF + kvr * KVSTR + kvc) * 2u;
        const unsigned vdst = kdst + (unsigned)KVBUF * 2u;
        const __half* ks = Kg + (size_t)(jt * 64 + kvr) * 64 + kvc;
        const __half* vs = Vg + (size_t)(jt * 64 + kvr) * 64 + kvc;
        cpa16(kdst,       ks);
        cpa16(kdst + 16u, ks + 8);
        cpa16(vdst,       vs);
        cpa16(vdst + 16u, vs + 8);
    };

    // prologue: 3 tiles in flight (empty commits if fewer tiles)
    prefetch_kv(0, 0); CPCOMMIT();
    if (1 < ntiles) prefetch_kv(1, 1);
    CPCOMMIT();
    if (2 < ntiles) prefetch_kv(2, 2);
    CPCOMMIT();

    for (int jt = 0; jt < ntiles; jt++) {
        CPWAIT2();
        __syncthreads();
        if (jt + 3 < ntiles) prefetch_kv(jt + 3, (jt + 3) & 3);
        CPCOMMIT();

        const int s = jt & 3;
        const unsigned kb = smb + (unsigned)(s * 2 * KVBUF) * 2u;
        const unsigned vb = kb + (unsigned)KVBUF * 2u;

        float sa[8][4];
#pragma unroll
        for (int i = 0; i < 8; i++)
#pragma unroll
            for (int j = 0; j < 4; j++) sa[i][j] = 0.f;

        {
            const int nrow = (lane & 7);
            const int kc = ((lane >> 3) & 3) * 8;
#pragma unroll
            for (int nf = 0; nf < 8; nf++) {
                unsigned b0, b1, b2, b3;
                ldsm4(kb + (unsigned)((nf * 8 + nrow) * KVSTR + kc) * 2u, b0, b1, b2, b3);
                mma16(sa[nf], qf[0], b0, b1);
                mma16(sa[nf], qf[1], b2, b3);
                ldsm4(kb + (unsigned)((nf * 8 + nrow) * KVSTR + 32 + kc) * 2u, b0, b1, b2, b3);
                mma16(sa[nf], qf[2], b0, b1);
                mma16(sa[nf], qf[3], b2, b3);
            }
        }

        if (jt * 64 + 63 > qt * 128 + wid * 16) {
#pragma unroll
            for (int nf = 0; nf < 8; nf++) {
                const int c = jt * 64 + nf * 8 + 2 * t;
                if (c > r0)     sa[nf][0] = -1e30f;
                if (c + 1 > r0) sa[nf][1] = -1e30f;
                if (c > r1)     sa[nf][2] = -1e30f;
                if (c + 1 > r1) sa[nf][3] = -1e30f;
            }
        }

        float mx0 = -1e30f, mx1 = -1e30f;
#pragma unroll
        for (int nf = 0; nf < 8; nf++) {
            mx0 = fmaxf(mx0, fmaxf(sa[nf][0], sa[nf][1]));
            mx1 = fmaxf(mx1, fmaxf(sa[nf][2], sa[nf][3]));
        }
        mx0 = fmaxf(mx0, __shfl_xor_sync(0xffffffffu, mx0, 1));
        mx0 = fmaxf(mx0, __shfl_xor_sync(0xffffffffu, mx0, 2));
        mx1 = fmaxf(mx1, __shfl_xor_sync(0xffffffffu, mx1, 1));
        mx1 = fmaxf(mx1, __shfl_xor_sync(0xffffffffu, mx1, 2));

        const float nm0 = fmaxf(m0, mx0);
        const float nm1 = fmaxf(m1, mx1);
        const float cr0 = ex2(m0 - nm0);
        const float cr1 = ex2(m1 - nm1);
        m0 = nm0; m1 = nm1;

        float ls0 = 0.f, ls1 = 0.f;
#pragma unroll
        for (int nf = 0; nf < 8; nf++) {
            sa[nf][0] = ex2(sa[nf][0] - nm0);
            sa[nf][1] = ex2(sa[nf][1] - nm0);
            sa[nf][2] = ex2(sa[nf][2] - nm1);
            sa[nf][3] = ex2(sa[nf][3] - nm1);
            ls0 += sa[nf][0] + sa[nf][1];
            ls1 += sa[nf][2] + sa[nf][3];
        }
        ls0 += __shfl_xor_sync(0xffffffffu, ls0, 1);
        ls0 += __shfl_xor_sync(0xffffffffu, ls0, 2);
        ls1 += __shfl_xor_sync(0xffffffffu, ls1, 1);
        ls1 += __shfl_xor_sync(0xffffffffu, ls1, 2);
        l0 = l0 * cr0 + ls0;
        l1 = l1 * cr1 + ls1;

#pragma unroll
        for (int df = 0; df < 8; df++) {
            of[df][0] *= cr0; of[df][1] *= cr0;
            of[df][2] *= cr1; of[df][3] *= cr1;
        }

        unsigned pf[4][4];
#pragma unroll
        for (int kc = 0; kc < 4; kc++) {
            pf[kc][0] = packh2(sa[2 * kc][0],     sa[2 * kc][1]);
            pf[kc][1] = packh2(sa[2 * kc][2],     sa[2 * kc][3]);
            pf[kc][2] = packh2(sa[2 * kc + 1][0], sa[2 * kc + 1][1]);
            pf[kc][3] = packh2(sa[2 * kc + 1][2], sa[2 * kc + 1][3]);
        }

        {
            const int vrow = (lane & 7) + ((lane >> 3) & 3) * 8;
#pragma unroll
            for (int df = 0; df < 8; df++) {
                unsigned b0, b1, b2, b3;
                ldsm4t(vb + (unsigned)(vrow * KVSTR + df * 8) * 2u, b0, b1, b2, b3);
                mma16(of[df], pf[0], b0, b1);
                mma16(of[df], pf[1], b2, b3);
                ldsm4t(vb + (unsigned)((vrow + 32) * KVSTR + df * 8) * 2u, b0, b1, b2, b3);
                mma16(of[df], pf[2], b0, b1);
                mma16(of[df], pf[3], b2, b3);
            }
        }
    }

    const int b = bh / NH;
    const int h = bh % NH;
    const float il0 = 1.f / l0;
    const float il1 = 1.f / l1;
#pragma unroll
    for (int df = 0; df < 8; df++) {
        const int col = h * 64 + df * 8 + 2 * t;
        *(__half2*)&g_Y[(size_t)(b * TSEQ + r0) * CDIM + col] =
            __floats2half2_rn(of[df][0] * il0, of[df][1] * il0);
        *(__half2*)&g_Y[(size_t)(b * TSEQ + r1) * CDIM + col] =
            __floats2half2_rn(of[df][2] * il1, of[df][3] * il1);
    }
}

// ---------------------------------------------------------------------------
extern "C" void kernel_launch(void* const* d_in, const int* in_sizes, int n_in,
                              void* d_out, int out_size)
{
    const float* x     = (const float*)d_in[0];
    const float* Wqkv  = (const float*)d_in[1];
    const float* bqkv  = (const float*)d_in[2];
    const float* Wproj = (const float*)d_in[3];
    const float* bproj = (const float*)d_in[4];
    float* out = (float*)d_out;

    __half *xh, *wqh, *wph;
    cudaGetSymbolAddress((void**)&xh,  g_Xh);
    cudaGetSymbolAddress((void**)&wqh, g_Wqkvh);
    cudaGetSymbolAddress((void**)&wph, g_Wprojh);

    cudaFuncSetAttribute(qkv_gemm_f16, cudaFuncAttributeMaxDynamicSharedMemorySize, GEMM_SMEM);
    cudaFuncSetAttribute(proj_gemm_f16, cudaFuncAttributeMaxDynamicSharedMemorySize, GEMM_SMEM);
    cudaFuncSetAttribute(attn_fa16, cudaFuncAttributeMaxDynamicSharedMemorySize, ATT_SMEM);

    f2h_kernel<<<(MTOK * CDIM) / 2048, 256>>>(x, xh, MTOK * CDIM);
    f2h_kernel<<<(CDIM * NQKV) / 2048, 256>>>(Wqkv, wqh, CDIM * NQKV);
    f2h_kernel<<<(CDIM * CDIM) / 2048, 256>>>(Wproj, wph, CDIM * CDIM);

    qkv_gemm_f16<<<dim3(NQKV / 128, MTOK / 128), 256, GEMM_SMEM>>>(bqkv);
    attn_fa16<<<dim3(TSEQ / 128, BH), 256, ATT_SMEM>>>();
    proj_gemm_f16<<<dim3(CDIM / 128, MTOK / 128), 256, GEMM_SMEM>>>(bproj, out);
}